// round 10
// baseline (speedup 1.0000x reference)
#include <cuda_runtime.h>
#include <cuda_fp16.h>
#include <math.h>

#define BB 2
#define LL 2048
#define DD 512
#define HH 8
#define DK 64
#define SK 40
#define UU 40
#define BH 16            // BB*HH
#define NROWS 32768      // BH*LL
#define NCH 16           // cumsum chunks per (b,h)
#define CH 128           // L per chunk

// ---------------- scratch (device globals; no allocation) ----------------
__device__ float g_q[BB*HH*LL*DK];
__device__ float g_k[BB*HH*LL*DK];
__device__ float g_v[BB*HH*LL*DK];
__device__ float g_scores[BH*UU*LL];
__device__ float g_M[NROWS];
__device__ int   g_Mtop[BH*UU];
__device__ int   g_rank[NROWS];
__device__ float g_mx[BH*UU];
__device__ float g_inv[BH*UU];
__device__ float g_part[BH*NCH*DK];
__device__ float g_offs[BH*NCH*DK];
__device__ float g_updp[8*BH*UU*DK];
__device__ int   g_idx[LL*SK];
// fp16x3 split operands (16B-aligned for float4 access)
__device__ __align__(16) __half g_xh[BB*LL*DD];
__device__ __align__(16) __half g_xl[BB*LL*DD];
__device__ __align__(16) __half g_wh[3*DD*DD];
__device__ __align__(16) __half g_wl[3*DD*DD];

// ---------------- kernel 0: normalize index_sample (int32 vs int64), 16 blocks ----------------
__global__ void k_idx(const unsigned int* __restrict__ raw, int nelem) {
    __shared__ int s_flag;
    int per = nelem / gridDim.x;
    int wbase = blockIdx.x * per;
    if (threadIdx.x == 0) s_flag = 0;
    __syncthreads();
    int local = 0;
    for (int j = threadIdx.x * 2 + 1; j < per; j += blockDim.x * 2)
        if (raw[wbase + j] != 0u) local = 1;
    if (local) atomicOr(&s_flag, 1);
    __syncthreads();
    int is32 = s_flag;
    int ebase = blockIdx.x * per;
    for (int e = ebase + threadIdx.x; e < ebase + per; e += blockDim.x)
        g_idx[e] = is32 ? (int)raw[e] : (int)raw[2 * e];
}

// ---------------- fp16 hi/lo split converters ----------------
__global__ void k_cvt_x(const float* __restrict__ x) {
    int i4 = blockIdx.x * blockDim.x + threadIdx.x;
    if (i4 >= BB*LL*DD/4) return;
    float4 v = ((const float4*)x)[i4];
    __half h0 = __float2half(v.x), h1 = __float2half(v.y);
    __half h2 = __float2half(v.z), h3 = __float2half(v.w);
    __half l0 = __float2half(v.x - __half2float(h0));
    __half l1 = __float2half(v.y - __half2float(h1));
    __half l2 = __float2half(v.z - __half2float(h2));
    __half l3 = __float2half(v.w - __half2float(h3));
    ((__half2*)g_xh)[i4*2]   = __halves2half2(h0, h1);
    ((__half2*)g_xh)[i4*2+1] = __halves2half2(h2, h3);
    ((__half2*)g_xl)[i4*2]   = __halves2half2(l0, l1);
    ((__half2*)g_xl)[i4*2+1] = __halves2half2(l2, l3);
}

__global__ void k_cvt_w(const float* __restrict__ Wq, const float* __restrict__ Wk,
                        const float* __restrict__ Wv) {
    int i4 = blockIdx.x * blockDim.x + threadIdx.x;
    int per = DD*DD/4;
    if (i4 >= 3*per) return;
    const float* src = (i4 < per) ? Wq : (i4 < 2*per) ? Wk : Wv;
    int j4 = (i4 < per) ? i4 : (i4 < 2*per) ? i4 - per : i4 - 2*per;
    float4 v = ((const float4*)src)[j4];
    __half h0 = __float2half(v.x), h1 = __float2half(v.y);
    __half h2 = __float2half(v.z), h3 = __float2half(v.w);
    __half l0 = __float2half(v.x - __half2float(h0));
    __half l1 = __float2half(v.y - __half2float(h1));
    __half l2 = __float2half(v.z - __half2float(h2));
    __half l3 = __float2half(v.w - __half2float(h3));
    ((__half2*)g_wh)[i4*2]   = __halves2half2(h0, h1);
    ((__half2*)g_wh)[i4*2+1] = __halves2half2(h2, h3);
    ((__half2*)g_wl)[i4*2]   = __halves2half2(l0, l1);
    ((__half2*)g_wl)[i4*2+1] = __halves2half2(l2, l3);
}

// ---------------- kernel 1: QKV projection via fp16x3 tensor-core mma ----------------
// Tile 128(M) x 64(N), k-slab = 32 halves (16 slabs), 3-stage cp.async ring.
#define SROW 40            // halves per smem row (32 data + 8 pad) = 80B; ldmatrix bank-clean
#define A_PB (128*SROW*2)  // A plane bytes: 10240
#define B_PB (64*SROW*2)   // B plane bytes: 5120
#define NSTAGE 3
#define BOFF (NSTAGE*2*A_PB)                       // 61440
#define GEMM_SMEM (NSTAGE*2*(A_PB + B_PB))         // 92160 bytes

#define CP_ASYNC16(dst, src) \
    asm volatile("cp.async.ca.shared.global [%0], [%1], 16;" :: "r"(dst), "l"(src))
#define CP_COMMIT() asm volatile("cp.async.commit_group;")
#define CP_WAIT1()  asm volatile("cp.async.wait_group 1;")
#define CP_WAIT0()  asm volatile("cp.async.wait_group 0;")

__device__ __forceinline__ void ldm4(unsigned int addr, unsigned int* r) {
    asm volatile("ldmatrix.sync.aligned.m8n8.x4.shared.b16 {%0,%1,%2,%3}, [%4];"
                 : "=r"(r[0]), "=r"(r[1]), "=r"(r[2]), "=r"(r[3]) : "r"(addr));
}
__device__ __forceinline__ void mma16816(float* c, const unsigned int* a, const unsigned int* b) {
    asm volatile("mma.sync.aligned.m16n8k16.row.col.f32.f16.f16.f32 "
                 "{%0,%1,%2,%3}, {%4,%5,%6,%7}, {%8,%9}, {%0,%1,%2,%3};"
                 : "+f"(c[0]), "+f"(c[1]), "+f"(c[2]), "+f"(c[3])
                 : "r"(a[0]), "r"(a[1]), "r"(a[2]), "r"(a[3]), "r"(b[0]), "r"(b[1]));
}

__global__ __launch_bounds__(256, 2) void gemm_mma(
    const float* __restrict__ bq, const float* __restrict__ bk, const float* __restrict__ bv) {
    extern __shared__ __align__(16) __half dsm[];
    int tid = threadIdx.x, lane = tid & 31, wid = tid >> 5;
    int warpM = wid >> 1, warpN = wid & 1;           // 4x2 warps -> 32x32 per warp
    int m0 = blockIdx.y * 128, n0 = blockIdx.x * 64; // N-tile = 64
    int w = n0 >> 9;
    const float* bias = (w == 0) ? bq : (w == 1) ? bk : bv;
    float* outp       = (w == 0) ? g_q : (w == 1) ? g_k : g_v;
    int i0 = n0 & 511;

    // A loads: 256 threads cover 128 rows x 2 chunk-pairs; each thread 2x16B per comp
    int grow = tid >> 1, gkh = tid & 1;              // chunk pair: halves offset gkh*16
    const __half* pxh = &g_xh[(size_t)(m0 + grow) * 512 + gkh * 16];
    const __half* pxl = &g_xl[(size_t)(m0 + grow) * 512 + gkh * 16];
    unsigned int a_off = (unsigned int)((grow * SROW + gkh * 16) * 2);   // bytes in plane
    // B loads: threads 0..127 cover 64 rows
    int brow = (tid & 127) >> 1, bkh2 = tid & 1;
    const __half* pwh = &g_wh[(size_t)(w * 512 + i0 + brow) * 512 + bkh2 * 16];
    const __half* pwl = &g_wl[(size_t)(w * 512 + i0 + brow) * 512 + bkh2 * 16];
    unsigned int b_off = (unsigned int)((brow * SROW + bkh2 * 16) * 2);
    bool bldr = tid < 128;
    unsigned int base = (unsigned int)__cvta_generic_to_shared(dsm);

    float acc[2][4][4];
    #pragma unroll
    for (int i = 0; i < 2; i++)
        #pragma unroll
        for (int j = 0; j < 4; j++)
            #pragma unroll
            for (int c = 0; c < 4; c++) acc[i][j][c] = 0.f;

    // prologue: slabs 0,1
    #pragma unroll
    for (int s = 0; s < 2; s++) {
        unsigned int sa = base + (s*2)*A_PB + a_off;
        CP_ASYNC16(sa,            pxh + s * 32);
        CP_ASYNC16(sa + 16,       pxh + s * 32 + 8);
        CP_ASYNC16(sa + A_PB,     pxl + s * 32);
        CP_ASYNC16(sa + A_PB + 16, pxl + s * 32 + 8);
        if (bldr) {
            unsigned int sb = base + BOFF + (s*2)*B_PB + b_off;
            CP_ASYNC16(sb,            pwh + s * 32);
            CP_ASYNC16(sb + 16,       pwh + s * 32 + 8);
            CP_ASYNC16(sb + B_PB,     pwl + s * 32);
            CP_ASYNC16(sb + B_PB + 16, pwl + s * 32 + 8);
        }
        CP_COMMIT();
    }

    int aRow = warpM * 32 + (lane & 15);
    int aKb  = (lane >> 4) * 8;                      // + ksub*16
    int bRow = warpN * 32 + 8 * (lane >> 4) + (lane & 7);
    int bKb  = ((lane >> 3) & 1) * 8;                // + ksub*16

    #pragma unroll 1
    for (int ks = 0; ks < 16; ks++) {
        int cur = ks % NSTAGE;
        if (ks < 15) { CP_WAIT1(); } else { CP_WAIT0(); }
        __syncthreads();

        if (ks + 2 < 16) {
            int st = (ks + 2) % NSTAGE;
            unsigned int sa = base + (st*2)*A_PB + a_off;
            CP_ASYNC16(sa,            pxh + (ks + 2) * 32);
            CP_ASYNC16(sa + 16,       pxh + (ks + 2) * 32 + 8);
            CP_ASYNC16(sa + A_PB,     pxl + (ks + 2) * 32);
            CP_ASYNC16(sa + A_PB + 16, pxl + (ks + 2) * 32 + 8);
            if (bldr) {
                unsigned int sb = base + BOFF + (st*2)*B_PB + b_off;
                CP_ASYNC16(sb,            pwh + (ks + 2) * 32);
                CP_ASYNC16(sb + 16,       pwh + (ks + 2) * 32 + 8);
                CP_ASYNC16(sb + B_PB,     pwl + (ks + 2) * 32);
                CP_ASYNC16(sb + B_PB + 16, pwl + (ks + 2) * 32 + 8);
            }
        }
        CP_COMMIT();

        #pragma unroll
        for (int ksub = 0; ksub < 2; ksub++) {
            int aK = ksub * 16 + aKb, bK = ksub * 16 + bKb;
            unsigned int afr[2][2][4];
            #pragma unroll
            for (int comp = 0; comp < 2; comp++)
                #pragma unroll
                for (int mt = 0; mt < 2; mt++) {
                    unsigned int ad = base + (cur*2 + comp)*A_PB +
                        (unsigned int)(((aRow + mt * 16) * SROW + aK) * 2);
                    ldm4(ad, afr[comp][mt]);
                }
            #pragma unroll
            for (int np = 0; np < 2; np++) {
                unsigned int bfr[2][4];
                #pragma unroll
                for (int comp = 0; comp < 2; comp++) {
                    unsigned int bd = base + BOFF + (cur*2 + comp)*B_PB +
                        (unsigned int)(((bRow + np * 16) * SROW + bK) * 2);
                    ldm4(bd, bfr[comp]);
                }
                #pragma unroll
                for (int mt = 0; mt < 2; mt++) {
                    #pragma unroll
                    for (int half = 0; half < 2; half++) {
                        int nt = np * 2 + half;
                        unsigned int bh_[2] = {bfr[0][half*2], bfr[0][half*2+1]};
                        unsigned int bl_[2] = {bfr[1][half*2], bfr[1][half*2+1]};
                        mma16816(acc[mt][nt], afr[0][mt], bh_);   // hi*hi
                        mma16816(acc[mt][nt], afr[0][mt], bl_);   // hi*lo
                        mma16816(acc[mt][nt], afr[1][mt], bh_);   // lo*hi
                    }
                }
            }
        }
    }

    // epilogue
    #pragma unroll
    for (int mt = 0; mt < 2; mt++) {
        int mr = m0 + warpM * 32 + mt * 16 + (lane >> 2);
        #pragma unroll
        for (int nt = 0; nt < 4; nt++) {
            int col = warpN * 32 + nt * 8 + 2 * (lane & 3);
            int i1 = i0 + col, i2 = i1 + 1;
            #pragma unroll
            for (int rh = 0; rh < 2; rh++) {
                int m = mr + rh * 8;
                int bh_ = (m >> 11) * HH;
                int l = m & 2047;
                float c0 = acc[mt][nt][rh*2], c1 = acc[mt][nt][rh*2+1];
                outp[((((size_t)(bh_ + (i1 >> 6))) << 11) + l) * 64 + (i1 & 63)] = c0 + bias[i1];
                outp[((((size_t)(bh_ + (i2 >> 6))) << 11) + l) * 64 + (i2 & 63)] = c1 + bias[i2];
            }
        }
    }
}

// ---------------- kernel 2: sampled scores -> M (coalesced gather) ----------------
__global__ __launch_bounds__(256) void k_sampleM() {
    __shared__ int sidx[8][SK];
    int wid = threadIdx.x >> 5, lane = threadIdx.x & 31;
    int row = blockIdx.x * 8 + wid;
    int bh = row >> 11, l = row & 2047;
    float4 qf = ((const float4*)(g_q + ((size_t)row << 6)))[lane & 15];
    sidx[wid][lane] = g_idx[l * SK + lane];
    if (lane < SK - 32) sidx[wid][lane + 32] = g_idx[l * SK + lane + 32];
    __syncwarp();
    int half = lane >> 4;
    float mx = -INFINITY, sm = 0.f;
    const float* kb = g_k + ((size_t)bh << 17);
    #pragma unroll
    for (int it = 0; it < SK / 2; it++) {
        int idx = sidx[wid][2 * it + half];
        float4 kf = ((const float4*)(kb + ((size_t)idx << 6)))[lane & 15];
        float p = qf.x*kf.x + qf.y*kf.y + qf.z*kf.z + qf.w*kf.w;
        p += __shfl_xor_sync(0xffffffffu, p, 1);
        p += __shfl_xor_sync(0xffffffffu, p, 2);
        p += __shfl_xor_sync(0xffffffffu, p, 4);
        p += __shfl_xor_sync(0xffffffffu, p, 8);
        mx = fmaxf(mx, p);
        sm += p;
    }
    mx = fmaxf(mx, __shfl_xor_sync(0xffffffffu, mx, 16));
    sm += __shfl_xor_sync(0xffffffffu, sm, 16);
    if (lane == 0) g_M[row] = mx - sm * (1.0f / LL);
}

// ---------------- kernel 3: exact top-40 via radix select ----------------
__global__ void k_topk() {
    __shared__ unsigned int uvals[LL];
    __shared__ int hist[256];
    __shared__ int suf[256];
    __shared__ unsigned int s_prefix;
    __shared__ int s_want, s_slot;
    int bh = blockIdx.x, t = threadIdx.x;
    for (int j = t; j < LL; j += 256) {
        unsigned int b = __float_as_uint(g_M[bh * LL + j]);
        uvals[j] = (b & 0x80000000u) ? ~b : (b | 0x80000000u);
        g_rank[bh * LL + j] = -1;
    }
    if (t == 0) { s_want = UU; s_prefix = 0u; s_slot = 0; }
    __syncthreads();

    #pragma unroll
    for (int level = 0; level < 4; level++) {
        int shift = 24 - level * 8;
        unsigned int mask = (level == 0) ? 0u : (0xFFFFFFFFu << (32 - 8 * level));
        hist[t] = 0;
        __syncthreads();
        unsigned int pref = s_prefix;
        int want = s_want;
        for (int j = t; j < LL; j += 256) {
            unsigned int u = uvals[j];
            if ((u & mask) == pref)
                atomicAdd(&hist[(u >> shift) & 0xFF], 1);
        }
        __syncthreads();
        suf[t] = hist[t];
        __syncthreads();
        #pragma unroll
        for (int o = 1; o < 256; o <<= 1) {
            int v = (t + o < 256) ? suf[t + o] : 0;
            __syncthreads();
            suf[t] += v;
            __syncthreads();
        }
        int above = (t < 255) ? suf[t + 1] : 0;
        if (suf[t] >= want && above < want) {
            s_prefix = pref | ((unsigned int)t << shift);
            s_want = want - above;
        }
        __syncthreads();
    }

    unsigned int T = s_prefix;
    int r = s_want;
    for (int j = t; j < LL; j += 256) {
        unsigned int u = uvals[j];
        bool sel = false;
        if (u > T) sel = true;
        else if (u == T) {
            int rank_eq = 0;
            for (int j2 = 0; j2 < j; j2++) if (uvals[j2] == T) rank_eq++;
            sel = (rank_eq < r);
        }
        if (sel) {
            int slot = atomicAdd(&s_slot, 1);
            g_Mtop[bh * UU + slot] = j;
            g_rank[bh * LL + j] = slot;
        }
    }
}

// ---------------- kernel 4: scores = scale * Qtop @ K^T ----------------
#define KT 64
__global__ void k_scores() {
    __shared__ float qtop[UU * DK];
    __shared__ float kt[KT * 65];
    int bh = blockIdx.y, l0 = blockIdx.x * KT, t = threadIdx.x;
    for (int j = t; j < UU * DK; j += 256) {
        int u = j >> 6, d = j & 63;
        int rl = g_Mtop[bh * UU + u];
        qtop[j] = g_q[((((size_t)bh << 11) + rl) << 6) + d];
    }
    for (int j = t; j < KT * DK; j += 256) {
        int li = j >> 6, d = j & 63;
        kt[li * 65 + d] = g_k[((((size_t)bh << 11) + l0 + li) << 6) + d];
    }
    __syncthreads();
    int lsub = t & 63, ug = t >> 6;
    float accv[10];
    #pragma unroll
    for (int g = 0; g < 10; g++) accv[g] = 0.f;
    for (int d = 0; d < 64; d++) {
        float kv = kt[lsub * 65 + d];
        #pragma unroll
        for (int g = 0; g < 10; g++)
            accv[g] += qtop[(ug + 4 * g) * 64 + d] * kv;
    }
    #pragma unroll
    for (int g = 0; g < 10; g++) {
        int u = ug + 4 * g;
        g_scores[((size_t)(bh * UU + u) << 11) + l0 + lsub] = accv[g] * 0.125f;
    }
}

// ---------------- kernel 5: softmax stats ----------------
__global__ void k_stats() {
    __shared__ float red[256];
    int r = blockIdx.x, t = threadIdx.x;
    const float* s = g_scores + ((size_t)r << 11);
    float mx = -INFINITY;
    for (int j = t; j < LL; j += 256) mx = fmaxf(mx, s[j]);
    red[t] = mx; __syncthreads();
    for (int o = 128; o; o >>= 1) { if (t < o) red[t] = fmaxf(red[t], red[t + o]); __syncthreads(); }
    mx = red[0]; __syncthreads();
    float sm = 0.f;
    for (int j = t; j < LL; j += 256) sm += expf(s[j] - mx);
    red[t] = sm; __syncthreads();
    for (int o = 128; o; o >>= 1) { if (t < o) red[t] += red[t + o]; __syncthreads(); }
    if (t == 0) { g_mx[r] = mx; g_inv[r] = 1.0f / red[0]; }
}

// ---------------- cumsum (context) ----------------
__global__ void k_csum_part() {
    __shared__ float red[256];
    int blk = blockIdx.x;
    int bh = blk >> 4, c = blk & 15;
    int t = threadIdx.x, d = t & 63, p = t >> 6;
    const float* vb = g_v + ((((size_t)bh << 11) + c * CH) << 6);
    float s = 0.f;
    for (int i = 0; i < 32; i++) s += vb[(p * 32 + i) * 64 + d];
    red[t] = s; __syncthreads();
    if (t < 64)
        g_part[blk * 64 + t] = red[t] + red[t + 64] + red[t + 128] + red[t + 192];
}

__global__ void k_csum_off() {
    int bh = blockIdx.x, d = threadIdx.x;
    float run = 0.f;
    for (int c = 0; c < NCH; c++) {
        g_offs[(bh * NCH + c) * 64 + d] = run;
        run += g_part[(bh * NCH + c) * 64 + d];
    }
}

__global__ void k_csum_scan(float* __restrict__ ctx) {
    __shared__ float vsh[CH * 64];
    int blk = blockIdx.x;
    int bh = blk >> 4, c = blk & 15;
    int t = threadIdx.x;
    const float4* vb = (const float4*)(g_v + ((((size_t)bh << 11) + c * CH) << 6));
    float4* vs4 = (float4*)vsh;
    for (int j = t; j < CH * 16; j += 256) vs4[j] = vb[j];
    __syncthreads();
    if (t < 64) {
        float run = g_offs[(bh * NCH + c) * 64 + t];
        for (int i = 0; i < CH; i++) { run += vsh[i * 64 + t]; vsh[i * 64 + t] = run; }
    }
    __syncthreads();
    float4* ob = (float4*)(ctx + ((((size_t)bh << 11) + c * CH) << 6));
    for (int j = t; j < CH * 16; j += 256) ob[j] = vs4[j];
}

// ---------------- kernel 7: upd partials = attn @ V ----------------
__global__ void k_upd() {
    __shared__ float vsh[64 * 64];
    __shared__ float ash[UU * 64];
    __shared__ float smx[UU], sinv[UU];
    int bh = blockIdx.y, ls = blockIdx.x;
    int t = threadIdx.x;
    if (t < UU) { smx[t] = g_mx[bh * UU + t]; sinv[t] = g_inv[bh * UU + t]; }

    int lane2 = (t & 31) * 2, ug = t >> 5;
    float acc[5][2];
    #pragma unroll
    for (int uu = 0; uu < 5; uu++) { acc[uu][0] = 0.f; acc[uu][1] = 0.f; }

    for (int tile = 0; tile < 4; tile++) {
        int l0 = ls * 256 + tile * 64;
        __syncthreads();
        const float4* vb = (const float4*)(g_v + ((((size_t)bh << 11) + l0) << 6));
        float4* vs4 = (float4*)vsh;
        for (int j = t; j < 64 * 16; j += 256) vs4[j] = vb[j];
        for (int j = t; j < UU * 64; j += 256) {
            int u = j >> 6, li = j & 63;
            ash[j] = expf(g_scores[((size_t)(bh * UU + u) << 11) + l0 + li] - smx[u]) * sinv[u];
        }
        __syncthreads();
        for (int li = 0; li < 64; li++) {
            float v0 = vsh[li * 64 + lane2], v1 = vsh[li * 64 + lane2 + 1];
            #pragma unroll
            for (int uu = 0; uu < 5; uu++) {
                float a = ash[(ug * 5 + uu) * 64 + li];
                acc[uu][0] += a * v0;
                acc[uu][1] += a * v1;
            }
        }
    }
    #pragma unroll
    for (int uu = 0; uu < 5; uu++) {
        int r = bh * UU + ug * 5 + uu;
        g_updp[((size_t)ls * BH * UU + r) * 64 + lane2]     = acc[uu][0];
        g_updp[((size_t)ls * BH * UU + r) * 64 + lane2 + 1] = acc[uu][1];
    }
}

// ---------------- kernel 8: reduce upd partials + scatter into context ----------------
__global__ void k_scatter(float* __restrict__ ctx) {
    int r = blockIdx.x, d = threadIdx.x;
    int bh = r / UU;
    int l = g_Mtop[r];
    float s = 0.f;
    #pragma unroll
    for (int p = 0; p < 8; p++) s += g_updp[((size_t)p * BH * UU + r) * 64 + d];
    ctx[((((size_t)bh << 11) + l) << 6) + d] = s;
}

// ---------------- kernel 9: attns output ----------------
__global__ void k_attns(float* __restrict__ attns) {
    int row = blockIdx.x;
    int bh = row >> 11;
    int r = g_rank[row];
    float* out = attns + ((size_t)row << 11);
    int t = threadIdx.x;
    if (r < 0) {
        float4 c = make_float4(1.0f / LL, 1.0f / LL, 1.0f / LL, 1.0f / LL);
        float4* o4 = (float4*)out;
        o4[t] = c;
        o4[t + 256] = c;
    } else {
        float mx = g_mx[bh * UU + r], inv = g_inv[bh * UU + r];
        const float* s = g_scores + ((size_t)(bh * UU + r) << 11);
        #pragma unroll
        for (int j = 0; j < 2; j++) {
            int base = (t + j * 256) * 4;
            float4 sv = *(const float4*)(s + base);
            float4 ov;
            ov.x = expf(sv.x - mx) * inv;
            ov.y = expf(sv.y - mx) * inv;
            ov.z = expf(sv.z - mx) * inv;
            ov.w = expf(sv.w - mx) * inv;
            *(float4*)(out + base) = ov;
        }
    }
}

// ---------------- launch ----------------
extern "C" void kernel_launch(void* const* d_in, const int* in_sizes, int n_in,
                              void* d_out, int out_size) {
    const float* x  = (const float*)d_in[0];
    const float* Wq = (const float*)d_in[1];
    const float* bq = (const float*)d_in[2];
    const float* Wk = (const float*)d_in[3];
    const float* bk = (const float*)d_in[4];
    const float* Wv = (const float*)d_in[5];
    const float* bv = (const float*)d_in[6];
    const unsigned int* idxraw = (const unsigned int*)d_in[7];

    float* ctx   = (float*)d_out;
    float* attns = ctx + (size_t)BB * LL * DD;

    static int smem_set = 0;
    if (!smem_set) {
        cudaFuncSetAttribute(gemm_mma, cudaFuncAttributeMaxDynamicSharedMemorySize, GEMM_SMEM);
        smem_set = 1;
    }

    k_idx<<<16, 512>>>(idxraw, LL * SK);
    k_cvt_x<<<(BB*LL*DD/4 + 255)/256, 256>>>(x);
    k_cvt_w<<<(3*DD*DD/4 + 255)/256, 256>>>(Wq, Wk, Wv);
    gemm_mma<<<dim3(24, 32), 256, GEMM_SMEM>>>(bq, bk, bv);   // profiled slot (4th)
    k_sampleM<<<NROWS / 8, 256>>>();
    k_topk<<<BH, 256>>>();
    k_scores<<<dim3(LL / KT, BH), 256>>>();
    k_stats<<<BH * UU, 256>>>();
    k_csum_part<<<BH * NCH, 256>>>();
    k_csum_off<<<BH, 64>>>();
    k_csum_scan<<<BH * NCH, 256>>>(ctx);
    k_upd<<<dim3(8, BH), 256>>>();
    k_scatter<<<BH * UU, 64>>>(ctx);
    k_attns<<<NROWS, 256>>>(attns);
}

// round 12
// speedup vs baseline: 1.0425x; 1.0425x over previous
#include <cuda_runtime.h>
#include <cuda_fp16.h>
#include <math.h>

#define BB 2
#define LL 2048
#define DD 512
#define HH 8
#define DK 64
#define SK 40
#define UU 40
#define BH 16            // BB*HH
#define NROWS 32768      // BH*LL
#define NCH 16           // cumsum chunks per (b,h)
#define CH 128           // L per chunk

// ---------------- scratch (device globals; no allocation) ----------------
__device__ float g_q[BB*HH*LL*DK];
__device__ float g_k[BB*HH*LL*DK];
__device__ float g_v[BB*HH*LL*DK];
__device__ float g_scores[BH*UU*LL];
__device__ float g_M[NROWS];
__device__ int   g_Mtop[BH*UU];
__device__ int   g_rank[NROWS];
__device__ float g_mx[BH*UU];
__device__ float g_inv[BH*UU];
__device__ float g_part[BH*NCH*DK];
__device__ float g_offs[BH*NCH*DK];
__device__ float g_updp[8*BH*UU*DK];
__device__ int   g_idx[LL*SK];
// fp16x3 split operands (16B-aligned for float4 access)
__device__ __align__(16) __half g_xh[BB*LL*DD];
__device__ __align__(16) __half g_xl[BB*LL*DD];
__device__ __align__(16) __half g_wh[3*DD*DD];
__device__ __align__(16) __half g_wl[3*DD*DD];

// ---------------- kernel 0: normalize index_sample (int32 vs int64), 16 blocks ----------------
__global__ void k_idx(const unsigned int* __restrict__ raw, int nelem) {
    __shared__ int s_flag;
    int per = nelem / gridDim.x;
    int wbase = blockIdx.x * per;
    if (threadIdx.x == 0) s_flag = 0;
    __syncthreads();
    int local = 0;
    for (int j = threadIdx.x * 2 + 1; j < per; j += blockDim.x * 2)
        if (raw[wbase + j] != 0u) local = 1;
    if (local) atomicOr(&s_flag, 1);
    __syncthreads();
    int is32 = s_flag;
    int ebase = blockIdx.x * per;
    for (int e = ebase + threadIdx.x; e < ebase + per; e += blockDim.x)
        g_idx[e] = is32 ? (int)raw[e] : (int)raw[2 * e];
}

// ---------------- fp16 hi/lo split converters ----------------
__global__ void k_cvt_x(const float* __restrict__ x) {
    int i4 = blockIdx.x * blockDim.x + threadIdx.x;
    if (i4 >= BB*LL*DD/4) return;
    float4 v = ((const float4*)x)[i4];
    __half h0 = __float2half(v.x), h1 = __float2half(v.y);
    __half h2 = __float2half(v.z), h3 = __float2half(v.w);
    __half l0 = __float2half(v.x - __half2float(h0));
    __half l1 = __float2half(v.y - __half2float(h1));
    __half l2 = __float2half(v.z - __half2float(h2));
    __half l3 = __float2half(v.w - __half2float(h3));
    ((__half2*)g_xh)[i4*2]   = __halves2half2(h0, h1);
    ((__half2*)g_xh)[i4*2+1] = __halves2half2(h2, h3);
    ((__half2*)g_xl)[i4*2]   = __halves2half2(l0, l1);
    ((__half2*)g_xl)[i4*2+1] = __halves2half2(l2, l3);
}

__global__ void k_cvt_w(const float* __restrict__ Wq, const float* __restrict__ Wk,
                        const float* __restrict__ Wv) {
    int i4 = blockIdx.x * blockDim.x + threadIdx.x;
    int per = DD*DD/4;
    if (i4 >= 3*per) return;
    const float* src = (i4 < per) ? Wq : (i4 < 2*per) ? Wk : Wv;
    int j4 = (i4 < per) ? i4 : (i4 < 2*per) ? i4 - per : i4 - 2*per;
    float4 v = ((const float4*)src)[j4];
    __half h0 = __float2half(v.x), h1 = __float2half(v.y);
    __half h2 = __float2half(v.z), h3 = __float2half(v.w);
    __half l0 = __float2half(v.x - __half2float(h0));
    __half l1 = __float2half(v.y - __half2float(h1));
    __half l2 = __float2half(v.z - __half2float(h2));
    __half l3 = __float2half(v.w - __half2float(h3));
    ((__half2*)g_wh)[i4*2]   = __halves2half2(h0, h1);
    ((__half2*)g_wh)[i4*2+1] = __halves2half2(h2, h3);
    ((__half2*)g_wl)[i4*2]   = __halves2half2(l0, l1);
    ((__half2*)g_wl)[i4*2+1] = __halves2half2(l2, l3);
}

// ---------------- kernel 1: QKV projection via fp16x3 tensor-core mma ----------------
// (Round-9 best config: 128x128 tile, k-slab 16 halves, 3-stage cp.async ring)
#define SROW 24            // halves per smem row (16 data + 8 pad) = 48B
#define PLANE (128*SROW)   // halves per plane (3072); 6144 B
#define NSTAGE 3
#define GEMM_SMEM (NSTAGE * 2 * 2 * PLANE * 2)   // 73728 bytes

#define CP_ASYNC16(dst, src) \
    asm volatile("cp.async.ca.shared.global [%0], [%1], 16;" :: "r"(dst), "l"(src))
#define CP_COMMIT() asm volatile("cp.async.commit_group;")
#define CP_WAIT1()  asm volatile("cp.async.wait_group 1;")
#define CP_WAIT0()  asm volatile("cp.async.wait_group 0;")

__device__ __forceinline__ void ldm4(unsigned int addr, unsigned int* r) {
    asm volatile("ldmatrix.sync.aligned.m8n8.x4.shared.b16 {%0,%1,%2,%3}, [%4];"
                 : "=r"(r[0]), "=r"(r[1]), "=r"(r[2]), "=r"(r[3]) : "r"(addr));
}
__device__ __forceinline__ void mma16816(float* c, const unsigned int* a, const unsigned int* b) {
    asm volatile("mma.sync.aligned.m16n8k16.row.col.f32.f16.f16.f32 "
                 "{%0,%1,%2,%3}, {%4,%5,%6,%7}, {%8,%9}, {%0,%1,%2,%3};"
                 : "+f"(c[0]), "+f"(c[1]), "+f"(c[2]), "+f"(c[3])
                 : "r"(a[0]), "r"(a[1]), "r"(a[2]), "r"(a[3]), "r"(b[0]), "r"(b[1]));
}

__global__ __launch_bounds__(256, 2) void gemm_mma(
    const float* __restrict__ bq, const float* __restrict__ bk, const float* __restrict__ bv) {
    extern __shared__ __align__(16) __half dsm[];
    int tid = threadIdx.x, lane = tid & 31, wid = tid >> 5;
    int warpM = wid >> 1, warpN = wid & 1;
    int m0 = blockIdx.y * 128, n0 = blockIdx.x * 128;
    int w = n0 >> 9;
    const float* bias = (w == 0) ? bq : (w == 1) ? bk : bv;
    float* outp       = (w == 0) ? g_q : (w == 1) ? g_k : g_v;
    int i0 = n0 & 511;

    int grow = tid >> 1, gkh = tid & 1;
    const __half* pxh = &g_xh[(size_t)(m0 + grow) * 512 + gkh * 8];
    const __half* pxl = &g_xl[(size_t)(m0 + grow) * 512 + gkh * 8];
    const __half* pwh = &g_wh[(size_t)(w * 512 + i0 + grow) * 512 + gkh * 8];
    const __half* pwl = &g_wl[(size_t)(w * 512 + i0 + grow) * 512 + gkh * 8];
    unsigned int dst_off = (unsigned int)((grow * SROW + gkh * 8) * 2);
    unsigned int base = (unsigned int)__cvta_generic_to_shared(dsm);
    const unsigned int PB = PLANE * 2;
    const unsigned int BOFF = 6 * PB;

    float acc[2][8][4];
    #pragma unroll
    for (int i = 0; i < 2; i++)
        #pragma unroll
        for (int j = 0; j < 8; j++)
            #pragma unroll
            for (int c = 0; c < 4; c++) acc[i][j][c] = 0.f;

    #pragma unroll
    for (int s = 0; s < 2; s++) {
        unsigned int sa = base + (s*2)*PB + dst_off;
        unsigned int sb = base + BOFF + (s*2)*PB + dst_off;
        CP_ASYNC16(sa,      pxh + s * 16);
        CP_ASYNC16(sa + PB, pxl + s * 16);
        CP_ASYNC16(sb,      pwh + s * 16);
        CP_ASYNC16(sb + PB, pwl + s * 16);
        CP_COMMIT();
    }

    int aRow = warpM * 32 + (lane & 15), aK = (lane >> 4) * 8;
    int bRow = warpN * 64 + 8 * (lane >> 4) + (lane & 7), bK = ((lane >> 3) & 1) * 8;

    #pragma unroll 1
    for (int ks = 0; ks < 32; ks++) {
        int cur = ks % NSTAGE;
        if (ks < 31) { CP_WAIT1(); } else { CP_WAIT0(); }
        __syncthreads();

        if (ks + 2 < 32) {
            int st = (ks + 2) % NSTAGE;
            unsigned int sa = base + (st*2)*PB + dst_off;
            unsigned int sb = base + BOFF + (st*2)*PB + dst_off;
            CP_ASYNC16(sa,      pxh + (ks + 2) * 16);
            CP_ASYNC16(sa + PB, pxl + (ks + 2) * 16);
            CP_ASYNC16(sb,      pwh + (ks + 2) * 16);
            CP_ASYNC16(sb + PB, pwl + (ks + 2) * 16);
            CP_COMMIT();
        }

        unsigned int afr[2][2][4];
        #pragma unroll
        for (int comp = 0; comp < 2; comp++)
            #pragma unroll
            for (int mt = 0; mt < 2; mt++) {
                unsigned int ad = base + (cur*2 + comp)*PB +
                    (unsigned int)(((aRow + mt * 16) * SROW + aK) * 2);
                ldm4(ad, afr[comp][mt]);
            }
        #pragma unroll
        for (int np = 0; np < 4; np++) {
            unsigned int bfr[2][4];
            #pragma unroll
            for (int comp = 0; comp < 2; comp++) {
                unsigned int bd = base + BOFF + (cur*2 + comp)*PB +
                    (unsigned int)(((bRow + np * 16) * SROW + bK) * 2);
                ldm4(bd, bfr[comp]);
            }
            #pragma unroll
            for (int mt = 0; mt < 2; mt++) {
                #pragma unroll
                for (int half = 0; half < 2; half++) {
                    int nt = np * 2 + half;
                    unsigned int bh_[2] = {bfr[0][half*2], bfr[0][half*2+1]};
                    unsigned int bl_[2] = {bfr[1][half*2], bfr[1][half*2+1]};
                    mma16816(acc[mt][nt], afr[0][mt], bh_);
                    mma16816(acc[mt][nt], afr[0][mt], bl_);
                    mma16816(acc[mt][nt], afr[1][mt], bh_);
                }
            }
        }
    }

    #pragma unroll
    for (int mt = 0; mt < 2; mt++) {
        int mr = m0 + warpM * 32 + mt * 16 + (lane >> 2);
        #pragma unroll
        for (int nt = 0; nt < 8; nt++) {
            int col = warpN * 64 + nt * 8 + 2 * (lane & 3);
            int i1 = i0 + col, i2 = i1 + 1;
            #pragma unroll
            for (int rh = 0; rh < 2; rh++) {
                int m = mr + rh * 8;
                int bh_ = (m >> 11) * HH;
                int l = m & 2047;
                float c0 = acc[mt][nt][rh*2], c1 = acc[mt][nt][rh*2+1];
                outp[((((size_t)(bh_ + (i1 >> 6))) << 11) + l) * 64 + (i1 & 63)] = c0 + bias[i1];
                outp[((((size_t)(bh_ + (i2 >> 6))) << 11) + l) * 64 + (i2 & 63)] = c1 + bias[i2];
            }
        }
    }
}

// ---------------- kernel 2: sampled scores -> M (coalesced gather) ----------------
__global__ __launch_bounds__(256) void k_sampleM() {
    __shared__ int sidx[8][SK];
    int wid = threadIdx.x >> 5, lane = threadIdx.x & 31;
    int row = blockIdx.x * 8 + wid;
    int bh = row >> 11, l = row & 2047;
    float4 qf = ((const float4*)(g_q + ((size_t)row << 6)))[lane & 15];
    sidx[wid][lane] = g_idx[l * SK + lane];
    if (lane < SK - 32) sidx[wid][lane + 32] = g_idx[l * SK + lane + 32];
    __syncwarp();
    int half = lane >> 4;
    float mx = -INFINITY, sm = 0.f;
    const float* kb = g_k + ((size_t)bh << 17);
    #pragma unroll
    for (int it = 0; it < SK / 2; it++) {
        int idx = sidx[wid][2 * it + half];
        float4 kf = ((const float4*)(kb + ((size_t)idx << 6)))[lane & 15];
        float p = qf.x*kf.x + qf.y*kf.y + qf.z*kf.z + qf.w*kf.w;
        p += __shfl_xor_sync(0xffffffffu, p, 1);
        p += __shfl_xor_sync(0xffffffffu, p, 2);
        p += __shfl_xor_sync(0xffffffffu, p, 4);
        p += __shfl_xor_sync(0xffffffffu, p, 8);
        mx = fmaxf(mx, p);
        sm += p;
    }
    mx = fmaxf(mx, __shfl_xor_sync(0xffffffffu, mx, 16));
    sm += __shfl_xor_sync(0xffffffffu, sm, 16);
    if (lane == 0) g_M[row] = mx - sm * (1.0f / LL);
}

// ---------------- kernel 3: exact top-40 via radix select ----------------
__global__ void k_topk() {
    __shared__ unsigned int uvals[LL];
    __shared__ int hist[256];
    __shared__ int suf[256];
    __shared__ unsigned int s_prefix;
    __shared__ int s_want, s_slot;
    int bh = blockIdx.x, t = threadIdx.x;
    for (int j = t; j < LL; j += 256) {
        unsigned int b = __float_as_uint(g_M[bh * LL + j]);
        uvals[j] = (b & 0x80000000u) ? ~b : (b | 0x80000000u);
        g_rank[bh * LL + j] = -1;
    }
    if (t == 0) { s_want = UU; s_prefix = 0u; s_slot = 0; }
    __syncthreads();

    #pragma unroll
    for (int level = 0; level < 4; level++) {
        int shift = 24 - level * 8;
        unsigned int mask = (level == 0) ? 0u : (0xFFFFFFFFu << (32 - 8 * level));
        hist[t] = 0;
        __syncthreads();
        unsigned int pref = s_prefix;
        int want = s_want;
        for (int j = t; j < LL; j += 256) {
            unsigned int u = uvals[j];
            if ((u & mask) == pref)
                atomicAdd(&hist[(u >> shift) & 0xFF], 1);
        }
        __syncthreads();
        suf[t] = hist[t];
        __syncthreads();
        #pragma unroll
        for (int o = 1; o < 256; o <<= 1) {
            int v = (t + o < 256) ? suf[t + o] : 0;
            __syncthreads();
            suf[t] += v;
            __syncthreads();
        }
        int above = (t < 255) ? suf[t + 1] : 0;
        if (suf[t] >= want && above < want) {
            s_prefix = pref | ((unsigned int)t << shift);
            s_want = want - above;
        }
        __syncthreads();
    }

    unsigned int T = s_prefix;
    int r = s_want;
    for (int j = t; j < LL; j += 256) {
        unsigned int u = uvals[j];
        bool sel = false;
        if (u > T) sel = true;
        else if (u == T) {
            int rank_eq = 0;
            for (int j2 = 0; j2 < j; j2++) if (uvals[j2] == T) rank_eq++;
            sel = (rank_eq < r);
        }
        if (sel) {
            int slot = atomicAdd(&s_slot, 1);
            g_Mtop[bh * UU + slot] = j;
            g_rank[bh * LL + j] = slot;
        }
    }
}

// ---------------- kernel 4: scores = scale * Qtop @ K^T ----------------
#define KT 64
__global__ void k_scores() {
    __shared__ float qtop[UU * DK];
    __shared__ float kt[KT * 65];
    int bh = blockIdx.y, l0 = blockIdx.x * KT, t = threadIdx.x;
    for (int j = t; j < UU * DK; j += 256) {
        int u = j >> 6, d = j & 63;
        int rl = g_Mtop[bh * UU + u];
        qtop[j] = g_q[((((size_t)bh << 11) + rl) << 6) + d];
    }
    for (int j = t; j < KT * DK; j += 256) {
        int li = j >> 6, d = j & 63;
        kt[li * 65 + d] = g_k[((((size_t)bh << 11) + l0 + li) << 6) + d];
    }
    __syncthreads();
    int lsub = t & 63, ug = t >> 6;
    float accv[10];
    #pragma unroll
    for (int g = 0; g < 10; g++) accv[g] = 0.f;
    for (int d = 0; d < 64; d++) {
        float kv = kt[lsub * 65 + d];
        #pragma unroll
        for (int g = 0; g < 10; g++)
            accv[g] += qtop[(ug + 4 * g) * 64 + d] * kv;
    }
    #pragma unroll
    for (int g = 0; g < 10; g++) {
        int u = ug + 4 * g;
        g_scores[((size_t)(bh * UU + u) << 11) + l0 + lsub] = accv[g] * 0.125f;
    }
}

// ---------------- kernel 5: softmax stats; overwrites scores with exp(s-mx) ----------------
__global__ void k_stats() {
    __shared__ float red[256];
    int r = blockIdx.x, t = threadIdx.x;
    float* s = g_scores + ((size_t)r << 11);
    float mx = -INFINITY;
    for (int j = t; j < LL; j += 256) mx = fmaxf(mx, s[j]);
    red[t] = mx; __syncthreads();
    for (int o = 128; o; o >>= 1) { if (t < o) red[t] = fmaxf(red[t], red[t + o]); __syncthreads(); }
    mx = red[0]; __syncthreads();
    float sm = 0.f;
    for (int j = t; j < LL; j += 256) {
        float e = expf(s[j] - mx);
        s[j] = e;                      // memoize exp once; upd/attns reuse
        sm += e;
    }
    red[t] = sm; __syncthreads();
    for (int o = 128; o; o >>= 1) { if (t < o) red[t] += red[t + o]; __syncthreads(); }
    if (t == 0) { g_mx[r] = mx; g_inv[r] = 1.0f / red[0]; }
}

// ---------------- cumsum (context) ----------------
__global__ void k_csum_part() {
    __shared__ float red[256];
    int blk = blockIdx.x;
    int bh = blk >> 4, c = blk & 15;
    int t = threadIdx.x, d = t & 63, p = t >> 6;
    const float* vb = g_v + ((((size_t)bh << 11) + c * CH) << 6);
    float s = 0.f;
    for (int i = 0; i < 32; i++) s += vb[(p * 32 + i) * 64 + d];
    red[t] = s; __syncthreads();
    if (t < 64)
        g_part[blk * 64 + t] = red[t] + red[t + 64] + red[t + 128] + red[t + 192];
}

__global__ void k_csum_off() {
    int bh = blockIdx.x, d = threadIdx.x;
    float run = 0.f;
    for (int c = 0; c < NCH; c++) {
        g_offs[(bh * NCH + c) * 64 + d] = run;
        run += g_part[(bh * NCH + c) * 64 + d];
    }
}

__global__ void k_csum_scan(float* __restrict__ ctx) {
    __shared__ float vsh[CH * 64];
    int blk = blockIdx.x;
    int bh = blk >> 4, c = blk & 15;
    int t = threadIdx.x;
    const float4* vb = (const float4*)(g_v + ((((size_t)bh << 11) + c * CH) << 6));
    float4* vs4 = (float4*)vsh;
    for (int j = t; j < CH * 16; j += 256) vs4[j] = vb[j];
    __syncthreads();
    if (t < 64) {
        float run = g_offs[(bh * NCH + c) * 64 + t];
        for (int i = 0; i < CH; i++) { run += vsh[i * 64 + t]; vsh[i * 64 + t] = run; }
    }
    __syncthreads();
    float4* ob = (float4*)(ctx + ((((size_t)bh << 11) + c * CH) << 6));
    for (int j = t; j < CH * 16; j += 256) ob[j] = vs4[j];
}

// ---------------- kernel 7: upd partials = attn @ V (scores already exp'd) ----------------
__global__ void k_upd() {
    __shared__ float vsh[64 * 64];
    __shared__ float ash[UU * 64];
    __shared__ float sinv[UU];
    int bh = blockIdx.y, ls = blockIdx.x;
    int t = threadIdx.x;
    if (t < UU) sinv[t] = g_inv[bh * UU + t];

    int lane2 = (t & 31) * 2, ug = t >> 5;
    float acc[5][2];
    #pragma unroll
    for (int uu = 0; uu < 5; uu++) { acc[uu][0] = 0.f; acc[uu][1] = 0.f; }

    for (int tile = 0; tile < 4; tile++) {
        int l0 = ls * 256 + tile * 64;
        __syncthreads();
        const float4* vb = (const float4*)(g_v + ((((size_t)bh << 11) + l0) << 6));
        float4* vs4 = (float4*)vsh;
        for (int j = t; j < 64 * 16; j += 256) vs4[j] = vb[j];
        for (int j = t; j < UU * 64; j += 256) {
            int u = j >> 6, li = j & 63;
            ash[j] = g_scores[((size_t)(bh * UU + u) << 11) + l0 + li] * sinv[u];
        }
        __syncthreads();
        for (int li = 0; li < 64; li++) {
            float v0 = vsh[li * 64 + lane2], v1 = vsh[li * 64 + lane2 + 1];
            #pragma unroll
            for (int uu = 0; uu < 5; uu++) {
                float a = ash[(ug * 5 + uu) * 64 + li];
                acc[uu][0] += a * v0;
                acc[uu][1] += a * v1;
            }
        }
    }
    #pragma unroll
    for (int uu = 0; uu < 5; uu++) {
        int r = bh * UU + ug * 5 + uu;
        g_updp[((size_t)ls * BH * UU + r) * 64 + lane2]     = acc[uu][0];
        g_updp[((size_t)ls * BH * UU + r) * 64 + lane2 + 1] = acc[uu][1];
    }
}

// ---------------- kernel 8: reduce upd partials + scatter into context ----------------
__global__ void k_scatter(float* __restrict__ ctx) {
    int r = blockIdx.x, d = threadIdx.x;
    int bh = r / UU;
    int l = g_Mtop[r];
    float s = 0.f;
    #pragma unroll
    for (int p = 0; p < 8; p++) s += g_updp[((size_t)p * BH * UU + r) * 64 + d];
    ctx[((((size_t)bh << 11) + l) << 6) + d] = s;
}

// ---------------- kernel 9: attns output (scores already exp'd) ----------------
__global__ void k_attns(float* __restrict__ attns) {
    int row = blockIdx.x;
    int bh = row >> 11;
    int r = g_rank[row];
    float* out = attns + ((size_t)row << 11);
    int t = threadIdx.x;
    if (r < 0) {
        float4 c = make_float4(1.0f / LL, 1.0f / LL, 1.0f / LL, 1.0f / LL);
        float4* o4 = (float4*)out;
        o4[t] = c;
        o4[t + 256] = c;
    } else {
        float inv = g_inv[bh * UU + r];
        const float* s = g_scores + ((size_t)(bh * UU + r) << 11);
        #pragma unroll
        for (int j = 0; j < 2; j++) {
            int base = (t + j * 256) * 4;
            float4 sv = *(const float4*)(s + base);
            float4 ov;
            ov.x = sv.x * inv;
            ov.y = sv.y * inv;
            ov.z = sv.z * inv;
            ov.w = sv.w * inv;
            *(float4*)(out + base) = ov;
        }
    }
}

// ---------------- launch ----------------
extern "C" void kernel_launch(void* const* d_in, const int* in_sizes, int n_in,
                              void* d_out, int out_size) {
    const float* x  = (const float*)d_in[0];
    const float* Wq = (const float*)d_in[1];
    const float* bq = (const float*)d_in[2];
    const float* Wk = (const float*)d_in[3];
    const float* bk = (const float*)d_in[4];
    const float* Wv = (const float*)d_in[5];
    const float* bv = (const float*)d_in[6];
    const unsigned int* idxraw = (const unsigned int*)d_in[7];

    float* ctx   = (float*)d_out;
    float* attns = ctx + (size_t)BB * LL * DD;

    static int smem_set = 0;
    if (!smem_set) {
        cudaFuncSetAttribute(gemm_mma, cudaFuncAttributeMaxDynamicSharedMemorySize, GEMM_SMEM);
        smem_set = 1;
    }

    k_idx<<<16, 512>>>(idxraw, LL * SK);
    k_cvt_x<<<(BB*LL*DD/4 + 255)/256, 256>>>(x);
    k_cvt_w<<<(3*DD*DD/4 + 255)/256, 256>>>(Wq, Wk, Wv);
    gemm_mma<<<dim3(12, 32), 256, GEMM_SMEM>>>(bq, bk, bv);   // profiled slot (4th)
    k_sampleM<<<NROWS / 8, 256>>>();
    k_topk<<<BH, 256>>>();
    k_scores<<<dim3(LL / KT, BH), 256>>>();
    k_stats<<<BH * UU, 256>>>();
    k_csum_part<<<BH * NCH, 256>>>();
    k_csum_off<<<BH, 64>>>();
    k_csum_scan<<<BH * NCH, 256>>>(ctx);
    k_upd<<<dim3(8, BH), 256>>>();
    k_scatter<<<BH * UU, 64>>>(ctx);
    k_attns<<<NROWS, 256>>>(attns);
}

// round 14
// speedup vs baseline: 1.1182x; 1.0726x over previous
#include <cuda_runtime.h>
#include <cuda_fp16.h>
#include <math.h>

#define BB 2
#define LL 2048
#define DD 512
#define HH 8
#define DK 64
#define SK 40
#define UU 40
#define BH 16            // BB*HH
#define NROWS 32768      // BH*LL
#define NCH 16           // cumsum chunks per (b,h)
#define CH 128           // L per chunk

// ---------------- scratch (device globals; no allocation) ----------------
__device__ float g_q[BB*HH*LL*DK];
__device__ float g_k[BB*HH*LL*DK];
__device__ float g_v[BB*HH*LL*DK];
__device__ float g_scores[BH*UU*LL];
__device__ float g_M[NROWS];
__device__ int   g_Mtop[BH*UU];
__device__ int   g_rank[NROWS];
__device__ float g_mx[BH*UU];
__device__ float g_inv[BH*UU];
__device__ float g_part[BH*NCH*DK];
__device__ float g_offs[BH*NCH*DK];
__device__ float g_updp[8*BH*UU*DK];
__device__ int   g_idx[LL*SK];
// fp16x3 split operands (16B-aligned for float4 access)
__device__ __align__(16) __half g_xh[BB*LL*DD];
__device__ __align__(16) __half g_xl[BB*LL*DD];
__device__ __align__(16) __half g_wh[3*DD*DD];
__device__ __align__(16) __half g_wl[3*DD*DD];

// ---------------- helpers ----------------
__device__ __forceinline__ void cvt_store(float4 v, __half2* dh, __half2* dl) {
    __half h0 = __float2half(v.x), h1 = __float2half(v.y);
    __half h2 = __float2half(v.z), h3 = __float2half(v.w);
    __half l0 = __float2half(v.x - __half2float(h0));
    __half l1 = __float2half(v.y - __half2float(h1));
    __half l2 = __float2half(v.z - __half2float(h2));
    __half l3 = __float2half(v.w - __half2float(h3));
    dh[0] = __halves2half2(h0, h1); dh[1] = __halves2half2(h2, h3);
    dl[0] = __halves2half2(l0, l1); dl[1] = __halves2half2(l2, l3);
}

// ---------------- launch 1: idx normalize + hi/lo split converters (union) ----------------
#define NCVX (BB*LL*DD/4/256)   // 2048 blocks for x
#define NCVW (3*DD*DD/4/256)    // 768 blocks for W
__global__ void k_pre(const unsigned int* __restrict__ raw,
                      const float* __restrict__ x, const float* __restrict__ Wq,
                      const float* __restrict__ Wk, const float* __restrict__ Wv) {
    int blk = blockIdx.x, t = threadIdx.x;
    if (blk < 16) {
        __shared__ int s_flag;
        const int nelem = LL * SK;
        int per = nelem / 16;
        int wbase = blk * per;
        if (t == 0) s_flag = 0;
        __syncthreads();
        int local = 0;
        for (int j = t * 2 + 1; j < per; j += 512)
            if (raw[wbase + j] != 0u) local = 1;
        if (local) atomicOr(&s_flag, 1);
        __syncthreads();
        int is32 = s_flag;
        for (int e = wbase + t; e < wbase + per; e += 256)
            g_idx[e] = is32 ? (int)raw[e] : (int)raw[2 * e];
    } else if (blk < 16 + NCVX) {
        int i4 = (blk - 16) * 256 + t;
        float4 v = ((const float4*)x)[i4];
        cvt_store(v, (__half2*)g_xh + i4*2, (__half2*)g_xl + i4*2);
    } else {
        int k = (blk - 16 - NCVX) * 256 + t;
        const int per = DD*DD/4;
        const float* src = (k < per) ? Wq : (k < 2*per) ? Wk : Wv;
        int j4 = (k < per) ? k : (k < 2*per) ? k - per : k - 2*per;
        float4 v = ((const float4*)src)[j4];
        cvt_store(v, (__half2*)g_wh + k*2, (__half2*)g_wl + k*2);
    }
}

// ---------------- launch 2: QKV projection via fp16x3 tensor-core mma ----------------
#define SROW 24            // halves per smem row (16 data + 8 pad) = 48B
#define PLANE (128*SROW)
#define NSTAGE 3
#define GEMM_SMEM (NSTAGE * 2 * 2 * PLANE * 2)   // 73728 bytes

#define CP_ASYNC16(dst, src) \
    asm volatile("cp.async.ca.shared.global [%0], [%1], 16;" :: "r"(dst), "l"(src))
#define CP_COMMIT() asm volatile("cp.async.commit_group;")
#define CP_WAIT1()  asm volatile("cp.async.wait_group 1;")
#define CP_WAIT0()  asm volatile("cp.async.wait_group 0;")

__device__ __forceinline__ void ldm4(unsigned int addr, unsigned int* r) {
    asm volatile("ldmatrix.sync.aligned.m8n8.x4.shared.b16 {%0,%1,%2,%3}, [%4];"
                 : "=r"(r[0]), "=r"(r[1]), "=r"(r[2]), "=r"(r[3]) : "r"(addr));
}
__device__ __forceinline__ void mma16816(float* c, const unsigned int* a, const unsigned int* b) {
    asm volatile("mma.sync.aligned.m16n8k16.row.col.f32.f16.f16.f32 "
                 "{%0,%1,%2,%3}, {%4,%5,%6,%7}, {%8,%9}, {%0,%1,%2,%3};"
                 : "+f"(c[0]), "+f"(c[1]), "+f"(c[2]), "+f"(c[3])
                 : "r"(a[0]), "r"(a[1]), "r"(a[2]), "r"(a[3]), "r"(b[0]), "r"(b[1]));
}

__global__ __launch_bounds__(256, 2) void gemm_mma(
    const float* __restrict__ bq, const float* __restrict__ bk, const float* __restrict__ bv) {
    extern __shared__ __align__(16) __half dsm[];
    int tid = threadIdx.x, lane = tid & 31, wid = tid >> 5;
    int warpM = wid >> 1, warpN = wid & 1;
    int m0 = blockIdx.y * 128, n0 = blockIdx.x * 128;
    int w = n0 >> 9;
    const float* bias = (w == 0) ? bq : (w == 1) ? bk : bv;
    float* outp       = (w == 0) ? g_q : (w == 1) ? g_k : g_v;
    int i0 = n0 & 511;

    int grow = tid >> 1, gkh = tid & 1;
    const __half* pxh = &g_xh[(size_t)(m0 + grow) * 512 + gkh * 8];
    const __half* pxl = &g_xl[(size_t)(m0 + grow) * 512 + gkh * 8];
    const __half* pwh = &g_wh[(size_t)(w * 512 + i0 + grow) * 512 + gkh * 8];
    const __half* pwl = &g_wl[(size_t)(w * 512 + i0 + grow) * 512 + gkh * 8];
    unsigned int dst_off = (unsigned int)((grow * SROW + gkh * 8) * 2);
    unsigned int base = (unsigned int)__cvta_generic_to_shared(dsm);
    const unsigned int PB = PLANE * 2;
    const unsigned int BOFF = 6 * PB;

    float acc[2][8][4];
    #pragma unroll
    for (int i = 0; i < 2; i++)
        #pragma unroll
        for (int j = 0; j < 8; j++)
            #pragma unroll
            for (int c = 0; c < 4; c++) acc[i][j][c] = 0.f;

    #pragma unroll
    for (int s = 0; s < 2; s++) {
        unsigned int sa = base + (s*2)*PB + dst_off;
        unsigned int sb = base + BOFF + (s*2)*PB + dst_off;
        CP_ASYNC16(sa,      pxh + s * 16);
        CP_ASYNC16(sa + PB, pxl + s * 16);
        CP_ASYNC16(sb,      pwh + s * 16);
        CP_ASYNC16(sb + PB, pwl + s * 16);
        CP_COMMIT();
    }

    int aRow = warpM * 32 + (lane & 15), aK = (lane >> 4) * 8;
    int bRow = warpN * 64 + 8 * (lane >> 4) + (lane & 7), bK = ((lane >> 3) & 1) * 8;

    #pragma unroll 1
    for (int ks = 0; ks < 32; ks++) {
        int cur = ks % NSTAGE;
        if (ks < 31) { CP_WAIT1(); } else { CP_WAIT0(); }
        __syncthreads();

        if (ks + 2 < 32) {
            int st = (ks + 2) % NSTAGE;
            unsigned int sa = base + (st*2)*PB + dst_off;
            unsigned int sb = base + BOFF + (st*2)*PB + dst_off;
            CP_ASYNC16(sa,      pxh + (ks + 2) * 16);
            CP_ASYNC16(sa + PB, pxl + (ks + 2) * 16);
            CP_ASYNC16(sb,      pwh + (ks + 2) * 16);
            CP_ASYNC16(sb + PB, pwl + (ks + 2) * 16);
            CP_COMMIT();
        }

        unsigned int afr[2][2][4];
        #pragma unroll
        for (int comp = 0; comp < 2; comp++)
            #pragma unroll
            for (int mt = 0; mt < 2; mt++) {
                unsigned int ad = base + (cur*2 + comp)*PB +
                    (unsigned int)(((aRow + mt * 16) * SROW + aK) * 2);
                ldm4(ad, afr[comp][mt]);
            }
        #pragma unroll
        for (int np = 0; np < 4; np++) {
            unsigned int bfr[2][4];
            #pragma unroll
            for (int comp = 0; comp < 2; comp++) {
                unsigned int bd = base + BOFF + (cur*2 + comp)*PB +
                    (unsigned int)(((bRow + np * 16) * SROW + bK) * 2);
                ldm4(bd, bfr[comp]);
            }
            #pragma unroll
            for (int mt = 0; mt < 2; mt++) {
                #pragma unroll
                for (int half = 0; half < 2; half++) {
                    int nt = np * 2 + half;
                    unsigned int bh_[2] = {bfr[0][half*2], bfr[0][half*2+1]};
                    unsigned int bl_[2] = {bfr[1][half*2], bfr[1][half*2+1]};
                    mma16816(acc[mt][nt], afr[0][mt], bh_);
                    mma16816(acc[mt][nt], afr[0][mt], bl_);
                    mma16816(acc[mt][nt], afr[1][mt], bh_);
                }
            }
        }
    }

    #pragma unroll
    for (int mt = 0; mt < 2; mt++) {
        int mr = m0 + warpM * 32 + mt * 16 + (lane >> 2);
        #pragma unroll
        for (int nt = 0; nt < 8; nt++) {
            int col = warpN * 64 + nt * 8 + 2 * (lane & 3);
            int i1 = i0 + col, i2 = i1 + 1;
            #pragma unroll
            for (int rh = 0; rh < 2; rh++) {
                int m = mr + rh * 8;
                int bh_ = (m >> 11) * HH;
                int l = m & 2047;
                float c0 = acc[mt][nt][rh*2], c1 = acc[mt][nt][rh*2+1];
                outp[((((size_t)(bh_ + (i1 >> 6))) << 11) + l) * 64 + (i1 & 63)] = c0 + bias[i1];
                outp[((((size_t)(bh_ + (i2 >> 6))) << 11) + l) * 64 + (i2 & 63)] = c1 + bias[i2];
            }
        }
    }
}

// ---------------- launch 3: sampled scores -> M (4096 blocks) ∥ csum_part (256 blocks) ----------------
__global__ __launch_bounds__(256) void k_samp_part() {
    int blk = blockIdx.x, t = threadIdx.x;
    if (blk < NROWS / 8) {
        __shared__ int sidx[8][SK];
        int wid = t >> 5, lane = t & 31;
        int row = blk * 8 + wid;
        int bh = row >> 11, l = row & 2047;
        float4 qf = ((const float4*)(g_q + ((size_t)row << 6)))[lane & 15];
        sidx[wid][lane] = g_idx[l * SK + lane];
        if (lane < SK - 32) sidx[wid][lane + 32] = g_idx[l * SK + lane + 32];
        __syncwarp();
        int half = lane >> 4;
        float mx = -INFINITY, sm = 0.f;
        const float* kb = g_k + ((size_t)bh << 17);
        #pragma unroll
        for (int it = 0; it < SK / 2; it++) {
            int idx = sidx[wid][2 * it + half];
            float4 kf = ((const float4*)(kb + ((size_t)idx << 6)))[lane & 15];
            float p = qf.x*kf.x + qf.y*kf.y + qf.z*kf.z + qf.w*kf.w;
            p += __shfl_xor_sync(0xffffffffu, p, 1);
            p += __shfl_xor_sync(0xffffffffu, p, 2);
            p += __shfl_xor_sync(0xffffffffu, p, 4);
            p += __shfl_xor_sync(0xffffffffu, p, 8);
            mx = fmaxf(mx, p);
            sm += p;
        }
        mx = fmaxf(mx, __shfl_xor_sync(0xffffffffu, mx, 16));
        sm += __shfl_xor_sync(0xffffffffu, sm, 16);
        if (lane == 0) g_M[row] = mx - sm * (1.0f / LL);
    } else {
        __shared__ float red[256];
        int b2 = blk - NROWS / 8;           // 0..255
        int bh = b2 >> 4, c = b2 & 15;
        int d = t & 63, p = t >> 6;
        const float* vb = g_v + ((((size_t)bh << 11) + c * CH) << 6);
        float s = 0.f;
        for (int i = 0; i < 32; i++) s += vb[(p * 32 + i) * 64 + d];
        red[t] = s; __syncthreads();
        if (t < 64)
            g_part[b2 * 64 + t] = red[t] + red[t + 64] + red[t + 128] + red[t + 192];
    }
}

// ---------------- launch 4: top-40 radix select (16 blocks) ∥ csum_off (16 blocks) ----------------
__global__ void k_topk_off() {
    int blk = blockIdx.x, t = threadIdx.x;
    if (blk >= BH) {
        int bh = blk - BH;
        if (t < 64) {
            float run = 0.f;
            for (int c = 0; c < NCH; c++) {
                g_offs[(bh * NCH + c) * 64 + t] = run;
                run += g_part[(bh * NCH + c) * 64 + t];
            }
        }
        return;
    }
    __shared__ unsigned int uvals[LL];
    __shared__ int hist[256];
    __shared__ int suf[256];
    __shared__ unsigned int s_prefix;
    __shared__ int s_want, s_slot;
    int bh = blk;
    for (int j = t; j < LL; j += 256) {
        unsigned int b = __float_as_uint(g_M[bh * LL + j]);
        uvals[j] = (b & 0x80000000u) ? ~b : (b | 0x80000000u);
        g_rank[bh * LL + j] = -1;
    }
    if (t == 0) { s_want = UU; s_prefix = 0u; s_slot = 0; }
    __syncthreads();

    #pragma unroll
    for (int level = 0; level < 4; level++) {
        int shift = 24 - level * 8;
        unsigned int mask = (level == 0) ? 0u : (0xFFFFFFFFu << (32 - 8 * level));
        hist[t] = 0;
        __syncthreads();
        unsigned int pref = s_prefix;
        int want = s_want;
        for (int j = t; j < LL; j += 256) {
            unsigned int u = uvals[j];
            if ((u & mask) == pref)
                atomicAdd(&hist[(u >> shift) & 0xFF], 1);
        }
        __syncthreads();
        suf[t] = hist[t];
        __syncthreads();
        #pragma unroll
        for (int o = 1; o < 256; o <<= 1) {
            int v = (t + o < 256) ? suf[t + o] : 0;
            __syncthreads();
            suf[t] += v;
            __syncthreads();
        }
        int above = (t < 255) ? suf[t + 1] : 0;
        if (suf[t] >= want && above < want) {
            s_prefix = pref | ((unsigned int)t << shift);
            s_want = want - above;
        }
        __syncthreads();
    }

    unsigned int T = s_prefix;
    int r = s_want;
    for (int j = t; j < LL; j += 256) {
        unsigned int u = uvals[j];
        bool sel = false;
        if (u > T) sel = true;
        else if (u == T) {
            int rank_eq = 0;
            for (int j2 = 0; j2 < j; j2++) if (uvals[j2] == T) rank_eq++;
            sel = (rank_eq < r);
        }
        if (sel) {
            int slot = atomicAdd(&s_slot, 1);
            g_Mtop[bh * UU + slot] = j;
            g_rank[bh * LL + j] = slot;
        }
    }
}

// ---------------- launch 5: scores (512 blocks) ∥ csum_scan (256 blocks) ----------------
// Shared 32KB buffer overlaid: scores branch uses qtop[2560]+kt[4160]=6720 floats;
// scan branch uses all 8192 floats as vsh.
#define KT 64
#define NSCBLK (BH * (LL / KT))     // 512
__global__ void k_scores_scan(float* __restrict__ ctx) {
    __shared__ float shp[CH * 64];          // 32768 bytes, dual-purpose
    int blk = blockIdx.x, t = threadIdx.x;
    if (blk < NSCBLK) {
        float* qtop = shp;                  // UU*DK = 2560 floats
        float* kt   = shp + UU * DK;        // KT*65 = 4160 floats
        int bh = blk >> 5, l0 = (blk & 31) * KT;
        for (int j = t; j < UU * DK; j += 256) {
            int u = j >> 6, d = j & 63;
            int rl = g_Mtop[bh * UU + u];
            qtop[j] = g_q[((((size_t)bh << 11) + rl) << 6) + d];
        }
        for (int j = t; j < KT * DK; j += 256) {
            int li = j >> 6, d = j & 63;
            kt[li * 65 + d] = g_k[((((size_t)bh << 11) + l0 + li) << 6) + d];
        }
        __syncthreads();
        int lsub = t & 63, ug = t >> 6;
        float accv[10];
        #pragma unroll
        for (int g = 0; g < 10; g++) accv[g] = 0.f;
        for (int d = 0; d < 64; d++) {
            float kv = kt[lsub * 65 + d];
            #pragma unroll
            for (int g = 0; g < 10; g++)
                accv[g] += qtop[(ug + 4 * g) * 64 + d] * kv;
        }
        #pragma unroll
        for (int g = 0; g < 10; g++) {
            int u = ug + 4 * g;
            g_scores[((size_t)(bh * UU + u) << 11) + l0 + lsub] = accv[g] * 0.125f;
        }
    } else {
        float* vsh = shp;                   // CH*64 = 8192 floats
        int b2 = blk - NSCBLK;              // 0..255
        int bh = b2 >> 4, c = b2 & 15;
        const float4* vb = (const float4*)(g_v + ((((size_t)bh << 11) + c * CH) << 6));
        float4* vs4 = (float4*)vsh;
        for (int j = t; j < CH * 16; j += 256) vs4[j] = vb[j];
        __syncthreads();
        if (t < 64) {
            float run = g_offs[(bh * NCH + c) * 64 + t];
            for (int i = 0; i < CH; i++) { run += vsh[i * 64 + t]; vsh[i * 64 + t] = run; }
        }
        __syncthreads();
        float4* ob = (float4*)(ctx + ((((size_t)bh << 11) + c * CH) << 6));
        for (int j = t; j < CH * 16; j += 256) ob[j] = vs4[j];
    }
}

// ---------------- launch 6: softmax stats; overwrites scores with exp(s-mx) ----------------
__global__ void k_stats() {
    __shared__ float red[256];
    int r = blockIdx.x, t = threadIdx.x;
    float* s = g_scores + ((size_t)r << 11);
    float mx = -INFINITY;
    for (int j = t; j < LL; j += 256) mx = fmaxf(mx, s[j]);
    red[t] = mx; __syncthreads();
    for (int o = 128; o; o >>= 1) { if (t < o) red[t] = fmaxf(red[t], red[t + o]); __syncthreads(); }
    mx = red[0]; __syncthreads();
    float sm = 0.f;
    for (int j = t; j < LL; j += 256) {
        float e = expf(s[j] - mx);
        s[j] = e;
        sm += e;
    }
    red[t] = sm; __syncthreads();
    for (int o = 128; o; o >>= 1) { if (t < o) red[t] += red[t + o]; __syncthreads(); }
    if (t == 0) { g_mx[r] = mx; g_inv[r] = 1.0f / red[0]; }
}

// ---------------- launch 7: upd partials = attn @ V ----------------
__global__ void k_upd() {
    __shared__ float vsh[64 * 64];
    __shared__ float ash[UU * 64];
    __shared__ float sinv[UU];
    int bh = blockIdx.y, ls = blockIdx.x;
    int t = threadIdx.x;
    if (t < UU) sinv[t] = g_inv[bh * UU + t];

    int lane2 = (t & 31) * 2, ug = t >> 5;
    float acc[5][2];
    #pragma unroll
    for (int uu = 0; uu < 5; uu++) { acc[uu][0] = 0.f; acc[uu][1] = 0.f; }

    for (int tile = 0; tile < 4; tile++) {
        int l0 = ls * 256 + tile * 64;
        __syncthreads();
        const float4* vb = (const float4*)(g_v + ((((size_t)bh << 11) + l0) << 6));
        float4* vs4 = (float4*)vsh;
        for (int j = t; j < 64 * 16; j += 256) vs4[j] = vb[j];
        for (int j = t; j < UU * 64; j += 256) {
            int u = j >> 6, li = j & 63;
            ash[j] = g_scores[((size_t)(bh * UU + u) << 11) + l0 + li] * sinv[u];
        }
        __syncthreads();
        for (int li = 0; li < 64; li++) {
            float v0 = vsh[li * 64 + lane2], v1 = vsh[li * 64 + lane2 + 1];
            #pragma unroll
            for (int uu = 0; uu < 5; uu++) {
                float a = ash[(ug * 5 + uu) * 64 + li];
                acc[uu][0] += a * v0;
                acc[uu][1] += a * v1;
            }
        }
    }
    #pragma unroll
    for (int uu = 0; uu < 5; uu++) {
        int r = bh * UU + ug * 5 + uu;
        g_updp[((size_t)ls * BH * UU + r) * 64 + lane2]     = acc[uu][0];
        g_updp[((size_t)ls * BH * UU + r) * 64 + lane2 + 1] = acc[uu][1];
    }
}

// ---------------- launch 8: attns output (32768 blocks) ∥ scatter (640 blocks) ----------------
__global__ void k_attns_scatter(float* __restrict__ ctx, float* __restrict__ attns) {
    int blk = blockIdx.x, t = threadIdx.x;
    if (blk >= NROWS) {
        int r = blk - NROWS;                // bh*UU + u
        if (t < 64) {
            int bh = r / UU;
            int l = g_Mtop[r];
            float s = 0.f;
            #pragma unroll
            for (int p = 0; p < 8; p++) s += g_updp[((size_t)p * BH * UU + r) * 64 + t];
            ctx[((((size_t)bh << 11) + l) << 6) + t] = s;
        }
        return;
    }
    int row = blk;
    int bh = row >> 11;
    int r = g_rank[row];
    float* out = attns + ((size_t)row << 11);
    if (r < 0) {
        float4 c = make_float4(1.0f / LL, 1.0f / LL, 1.0f / LL, 1.0f / LL);
        float4* o4 = (float4*)out;
        o4[t] = c;
        o4[t + 256] = c;
    } else {
        float inv = g_inv[bh * UU + r];
        const float* s = g_scores + ((size_t)(bh * UU + r) << 11);
        #pragma unroll
        for (int j = 0; j < 2; j++) {
            int base = (t + j * 256) * 4;
            float4 sv = *(const float4*)(s + base);
            float4 ov;
            ov.x = sv.x * inv;
            ov.y = sv.y * inv;
            ov.z = sv.z * inv;
            ov.w = sv.w * inv;
            *(float4*)(out + base) = ov;
        }
    }
}

// ---------------- launch ----------------
extern "C" void kernel_launch(void* const* d_in, const int* in_sizes, int n_in,
                              void* d_out, int out_size) {
    const float* x  = (const float*)d_in[0];
    const float* Wq = (const float*)d_in[1];
    const float* bq = (const float*)d_in[2];
    const float* Wk = (const float*)d_in[3];
    const float* bk = (const float*)d_in[4];
    const float* Wv = (const float*)d_in[5];
    const float* bv = (const float*)d_in[6];
    const unsigned int* idxraw = (const unsigned int*)d_in[7];

    float* ctx   = (float*)d_out;
    float* attns = ctx + (size_t)BB * LL * DD;

    static int smem_set = 0;
    if (!smem_set) {
        cudaFuncSetAttribute(gemm_mma, cudaFuncAttributeMaxDynamicSharedMemorySize, GEMM_SMEM);
        smem_set = 1;
    }

    k_pre<<<16 + NCVX + NCVW, 256>>>(idxraw, x, Wq, Wk, Wv);
    gemm_mma<<<dim3(12, 32), 256, GEMM_SMEM>>>(bq, bk, bv);
    k_samp_part<<<NROWS / 8 + BH * NCH, 256>>>();
    k_topk_off<<<BH * 2, 256>>>();
    k_scores_scan<<<NSCBLK + BH * NCH, 256>>>(ctx);
    k_stats<<<BH * UU, 256>>>();
    k_upd<<<dim3(8, BH), 256>>>();
    k_attns_scatter<<<NROWS + BH * UU, 256>>>(ctx, attns);
}

// round 16
// speedup vs baseline: 1.1286x; 1.0093x over previous
#include <cuda_runtime.h>
#include <cuda_fp16.h>
#include <math.h>

#define BB 2
#define LL 2048
#define DD 512
#define HH 8
#define DK 64
#define SK 40
#define UU 40
#define BH 16            // BB*HH
#define NROWS 32768      // BH*LL
#define NCH 16           // cumsum chunks per (b,h)
#define CH 128           // L per chunk

// ---------------- scratch (device globals; no allocation) ----------------
__device__ float g_q[BB*HH*LL*DK];
__device__ float g_k[BB*HH*LL*DK];
__device__ float g_v[BB*HH*LL*DK];
__device__ float g_scores[BH*UU*LL];
__device__ float g_M[NROWS];
__device__ int   g_Mtop[BH*UU];
__device__ int   g_rank[NROWS];
__device__ float g_mx[BH*UU];
__device__ float g_inv[BH*UU];
__device__ float g_part[BH*NCH*DK];
__device__ float g_offs[BH*NCH*DK];
__device__ float g_updp[8*BH*UU*DK];
__device__ int   g_idx[LL*SK];
// fp16x3 split operands (16B-aligned for float4 access)
__device__ __align__(16) __half g_xh[BB*LL*DD];
__device__ __align__(16) __half g_xl[BB*LL*DD];
__device__ __align__(16) __half g_wh[3*DD*DD];
__device__ __align__(16) __half g_wl[3*DD*DD];

// ---------------- helpers ----------------
__device__ __forceinline__ void cvt_store(float4 v, __half2* dh, __half2* dl) {
    __half h0 = __float2half(v.x), h1 = __float2half(v.y);
    __half h2 = __float2half(v.z), h3 = __float2half(v.w);
    __half l0 = __float2half(v.x - __half2float(h0));
    __half l1 = __float2half(v.y - __half2float(h1));
    __half l2 = __float2half(v.z - __half2float(h2));
    __half l3 = __float2half(v.w - __half2float(h3));
    dh[0] = __halves2half2(h0, h1); dh[1] = __halves2half2(h2, h3);
    dl[0] = __halves2half2(l0, l1); dl[1] = __halves2half2(l2, l3);
}

// ---------------- launch 1: idx normalize + hi/lo split converters (union) ----------------
#define NCVX (BB*LL*DD/4/256)   // 2048 blocks for x
#define NCVW (3*DD*DD/4/256)    // 768 blocks for W
__global__ void k_pre(const unsigned int* __restrict__ raw,
                      const float* __restrict__ x, const float* __restrict__ Wq,
                      const float* __restrict__ Wk, const float* __restrict__ Wv) {
    int blk = blockIdx.x, t = threadIdx.x;
    if (blk < 16) {
        __shared__ int s_flag;
        const int nelem = LL * SK;
        int per = nelem / 16;
        int wbase = blk * per;
        if (t == 0) s_flag = 0;
        __syncthreads();
        int local = 0;
        for (int j = t * 2 + 1; j < per; j += 512)
            if (raw[wbase + j] != 0u) local = 1;
        if (local) atomicOr(&s_flag, 1);
        __syncthreads();
        int is32 = s_flag;
        for (int e = wbase + t; e < wbase + per; e += 256)
            g_idx[e] = is32 ? (int)raw[e] : (int)raw[2 * e];
    } else if (blk < 16 + NCVX) {
        int i4 = (blk - 16) * 256 + t;
        float4 v = ((const float4*)x)[i4];
        cvt_store(v, (__half2*)g_xh + i4*2, (__half2*)g_xl + i4*2);
    } else {
        int k = (blk - 16 - NCVX) * 256 + t;
        const int per = DD*DD/4;
        const float* src = (k < per) ? Wq : (k < 2*per) ? Wk : Wv;
        int j4 = (k < per) ? k : (k < 2*per) ? k - per : k - 2*per;
        float4 v = ((const float4*)src)[j4];
        cvt_store(v, (__half2*)g_wh + k*2, (__half2*)g_wl + k*2);
    }
}

// ---------------- launch 2: QKV projection via fp16x3 tensor-core mma ----------------
#define SROW 24            // halves per smem row (16 data + 8 pad) = 48B
#define PLANE (128*SROW)
#define NSTAGE 3
#define GEMM_SMEM (NSTAGE * 2 * 2 * PLANE * 2)   // 73728 bytes

#define CP_ASYNC16(dst, src) \
    asm volatile("cp.async.ca.shared.global [%0], [%1], 16;" :: "r"(dst), "l"(src))
#define CP_COMMIT() asm volatile("cp.async.commit_group;")
#define CP_WAIT1()  asm volatile("cp.async.wait_group 1;")
#define CP_WAIT0()  asm volatile("cp.async.wait_group 0;")

__device__ __forceinline__ void ldm4(unsigned int addr, unsigned int* r) {
    asm volatile("ldmatrix.sync.aligned.m8n8.x4.shared.b16 {%0,%1,%2,%3}, [%4];"
                 : "=r"(r[0]), "=r"(r[1]), "=r"(r[2]), "=r"(r[3]) : "r"(addr));
}
__device__ __forceinline__ void mma16816(float* c, const unsigned int* a, const unsigned int* b) {
    asm volatile("mma.sync.aligned.m16n8k16.row.col.f32.f16.f16.f32 "
                 "{%0,%1,%2,%3}, {%4,%5,%6,%7}, {%8,%9}, {%0,%1,%2,%3};"
                 : "+f"(c[0]), "+f"(c[1]), "+f"(c[2]), "+f"(c[3])
                 : "r"(a[0]), "r"(a[1]), "r"(a[2]), "r"(a[3]), "r"(b[0]), "r"(b[1]));
}

__global__ __launch_bounds__(256, 2) void gemm_mma(
    const float* __restrict__ bq, const float* __restrict__ bk, const float* __restrict__ bv) {
    extern __shared__ __align__(16) __half dsm[];
    int tid = threadIdx.x, lane = tid & 31, wid = tid >> 5;
    int warpM = wid >> 1, warpN = wid & 1;
    int m0 = blockIdx.y * 128, n0 = blockIdx.x * 128;
    int w = n0 >> 9;
    const float* bias = (w == 0) ? bq : (w == 1) ? bk : bv;
    float* outp       = (w == 0) ? g_q : (w == 1) ? g_k : g_v;
    int i0 = n0 & 511;

    int grow = tid >> 1, gkh = tid & 1;
    const __half* pxh = &g_xh[(size_t)(m0 + grow) * 512 + gkh * 8];
    const __half* pxl = &g_xl[(size_t)(m0 + grow) * 512 + gkh * 8];
    const __half* pwh = &g_wh[(size_t)(w * 512 + i0 + grow) * 512 + gkh * 8];
    const __half* pwl = &g_wl[(size_t)(w * 512 + i0 + grow) * 512 + gkh * 8];
    unsigned int dst_off = (unsigned int)((grow * SROW + gkh * 8) * 2);
    unsigned int base = (unsigned int)__cvta_generic_to_shared(dsm);
    const unsigned int PB = PLANE * 2;
    const unsigned int BOFF = 6 * PB;

    float acc[2][8][4];
    #pragma unroll
    for (int i = 0; i < 2; i++)
        #pragma unroll
        for (int j = 0; j < 8; j++)
            #pragma unroll
            for (int c = 0; c < 4; c++) acc[i][j][c] = 0.f;

    #pragma unroll
    for (int s = 0; s < 2; s++) {
        unsigned int sa = base + (s*2)*PB + dst_off;
        unsigned int sb = base + BOFF + (s*2)*PB + dst_off;
        CP_ASYNC16(sa,      pxh + s * 16);
        CP_ASYNC16(sa + PB, pxl + s * 16);
        CP_ASYNC16(sb,      pwh + s * 16);
        CP_ASYNC16(sb + PB, pwl + s * 16);
        CP_COMMIT();
    }

    int aRow = warpM * 32 + (lane & 15), aK = (lane >> 4) * 8;
    int bRow = warpN * 64 + 8 * (lane >> 4) + (lane & 7), bK = ((lane >> 3) & 1) * 8;

    #pragma unroll 1
    for (int ks = 0; ks < 32; ks++) {
        int cur = ks % NSTAGE;
        if (ks < 31) { CP_WAIT1(); } else { CP_WAIT0(); }
        __syncthreads();

        if (ks + 2 < 32) {
            int st = (ks + 2) % NSTAGE;
            unsigned int sa = base + (st*2)*PB + dst_off;
            unsigned int sb = base + BOFF + (st*2)*PB + dst_off;
            CP_ASYNC16(sa,      pxh + (ks + 2) * 16);
            CP_ASYNC16(sa + PB, pxl + (ks + 2) * 16);
            CP_ASYNC16(sb,      pwh + (ks + 2) * 16);
            CP_ASYNC16(sb + PB, pwl + (ks + 2) * 16);
            CP_COMMIT();
        }

        unsigned int afr[2][2][4];
        #pragma unroll
        for (int comp = 0; comp < 2; comp++)
            #pragma unroll
            for (int mt = 0; mt < 2; mt++) {
                unsigned int ad = base + (cur*2 + comp)*PB +
                    (unsigned int)(((aRow + mt * 16) * SROW + aK) * 2);
                ldm4(ad, afr[comp][mt]);
            }
        #pragma unroll
        for (int np = 0; np < 4; np++) {
            unsigned int bfr[2][4];
            #pragma unroll
            for (int comp = 0; comp < 2; comp++) {
                unsigned int bd = base + BOFF + (cur*2 + comp)*PB +
                    (unsigned int)(((bRow + np * 16) * SROW + bK) * 2);
                ldm4(bd, bfr[comp]);
            }
            #pragma unroll
            for (int mt = 0; mt < 2; mt++) {
                #pragma unroll
                for (int half = 0; half < 2; half++) {
                    int nt = np * 2 + half;
                    unsigned int bh_[2] = {bfr[0][half*2], bfr[0][half*2+1]};
                    unsigned int bl_[2] = {bfr[1][half*2], bfr[1][half*2+1]};
                    mma16816(acc[mt][nt], afr[0][mt], bh_);
                    mma16816(acc[mt][nt], afr[0][mt], bl_);
                    mma16816(acc[mt][nt], afr[1][mt], bh_);
                }
            }
        }
    }

    #pragma unroll
    for (int mt = 0; mt < 2; mt++) {
        int mr = m0 + warpM * 32 + mt * 16 + (lane >> 2);
        #pragma unroll
        for (int nt = 0; nt < 8; nt++) {
            int col = warpN * 64 + nt * 8 + 2 * (lane & 3);
            int i1 = i0 + col, i2 = i1 + 1;
            #pragma unroll
            for (int rh = 0; rh < 2; rh++) {
                int m = mr + rh * 8;
                int bh_ = (m >> 11) * HH;
                int l = m & 2047;
                float c0 = acc[mt][nt][rh*2], c1 = acc[mt][nt][rh*2+1];
                outp[((((size_t)(bh_ + (i1 >> 6))) << 11) + l) * 64 + (i1 & 63)] = c0 + bias[i1];
                outp[((((size_t)(bh_ + (i2 >> 6))) << 11) + l) * 64 + (i2 & 63)] = c1 + bias[i2];
            }
        }
    }
}

// ---------------- launch 3: sampled scores -> M (4096 blocks) ∥ csum_part (256 blocks) ----------------
__global__ __launch_bounds__(256) void k_samp_part() {
    int blk = blockIdx.x, t = threadIdx.x;
    if (blk < NROWS / 8) {
        __shared__ int sidx[8][SK];
        int wid = t >> 5, lane = t & 31;
        int row = blk * 8 + wid;
        int bh = row >> 11, l = row & 2047;
        float4 qf = ((const float4*)(g_q + ((size_t)row << 6)))[lane & 15];
        sidx[wid][lane] = g_idx[l * SK + lane];
        if (lane < SK - 32) sidx[wid][lane + 32] = g_idx[l * SK + lane + 32];
        __syncwarp();
        int half = lane >> 4;
        float mx = -INFINITY, sm = 0.f;
        const float* kb = g_k + ((size_t)bh << 17);
        #pragma unroll
        for (int it = 0; it < SK / 2; it++) {
            int idx = sidx[wid][2 * it + half];
            float4 kf = ((const float4*)(kb + ((size_t)idx << 6)))[lane & 15];
            float p = qf.x*kf.x + qf.y*kf.y + qf.z*kf.z + qf.w*kf.w;
            p += __shfl_xor_sync(0xffffffffu, p, 1);
            p += __shfl_xor_sync(0xffffffffu, p, 2);
            p += __shfl_xor_sync(0xffffffffu, p, 4);
            p += __shfl_xor_sync(0xffffffffu, p, 8);
            mx = fmaxf(mx, p);
            sm += p;
        }
        mx = fmaxf(mx, __shfl_xor_sync(0xffffffffu, mx, 16));
        sm += __shfl_xor_sync(0xffffffffu, sm, 16);
        if (lane == 0) g_M[row] = mx - sm * (1.0f / LL);
    } else {
        __shared__ float red[256];
        int b2 = blk - NROWS / 8;           // 0..255
        int bh = b2 >> 4, c = b2 & 15;
        int d = t & 63, p = t >> 6;
        const float* vb = g_v + ((((size_t)bh << 11) + c * CH) << 6);
        float s = 0.f;
        for (int i = 0; i < 32; i++) s += vb[(p * 32 + i) * 64 + d];
        red[t] = s; __syncthreads();
        if (t < 64)
            g_part[b2 * 64 + t] = red[t] + red[t + 64] + red[t + 128] + red[t + 192];
    }
}

// ---------------- launch 4: top-40 radix select (warp-scan bins) ∥ csum_off ----------------
__global__ void k_topk_off() {
    int blk = blockIdx.x, t = threadIdx.x;
    if (blk >= BH) {
        int bh = blk - BH;
        if (t < 64) {
            float run = 0.f;
            for (int c = 0; c < NCH; c++) {
                g_offs[(bh * NCH + c) * 64 + t] = run;
                run += g_part[(bh * NCH + c) * 64 + t];
            }
        }
        return;
    }
    __shared__ unsigned int uvals[LL];
    __shared__ int hist[256];
    __shared__ unsigned int s_prefix;
    __shared__ int s_want, s_slot;
    int bh = blk;
    for (int j = t; j < LL; j += 256) {
        unsigned int b = __float_as_uint(g_M[bh * LL + j]);
        uvals[j] = (b & 0x80000000u) ? ~b : (b | 0x80000000u);
        g_rank[bh * LL + j] = -1;
    }
    if (t == 0) { s_want = UU; s_prefix = 0u; s_slot = 0; }
    __syncthreads();

    #pragma unroll
    for (int level = 0; level < 4; level++) {
        int shift = 24 - level * 8;
        unsigned int mask = (level == 0) ? 0u : (0xFFFFFFFFu << (32 - 8 * level));
        hist[t] = 0;
        __syncthreads();
        unsigned int pref = s_prefix;
        for (int j = t; j < LL; j += 256) {
            unsigned int u = uvals[j];
            if ((u & mask) == pref)
                atomicAdd(&hist[(u >> shift) & 0xFF], 1);
        }
        __syncthreads();
        // warp 0: suffix-scan 256 bins (8 per lane) via shfl; pick crossing bin
        if (t < 32) {
            int base_ = t * 8;
            int loc[8];
            int s = 0;
            #pragma unroll
            for (int i = 7; i >= 0; i--) { s += hist[base_ + i]; loc[i] = s; }
            // inclusive suffix scan over lane totals
            int hi = s;
            #pragma unroll
            for (int o = 1; o < 32; o <<= 1) {
                int v = __shfl_down_sync(0xffffffffu, hi, o);
                if (t + o < 32) hi += v;
            }
            int above_lanes = hi - s;       // sum of totals for lanes > t
            int want = s_want;
            #pragma unroll
            for (int i = 0; i < 8; i++) {
                int sfx = loc[i] + above_lanes;
                int abv = ((i < 7) ? loc[i + 1] : 0) + above_lanes;
                if (sfx >= want && abv < want) {
                    s_prefix = pref | ((unsigned int)(base_ + i) << shift);
                    s_want = want - abv;
                }
            }
        }
        __syncthreads();
    }

    unsigned int T = s_prefix;
    int r = s_want;
    for (int j = t; j < LL; j += 256) {
        unsigned int u = uvals[j];
        bool sel = false;
        if (u > T) sel = true;
        else if (u == T) {
            int rank_eq = 0;
            for (int j2 = 0; j2 < j; j2++) if (uvals[j2] == T) rank_eq++;
            sel = (rank_eq < r);
        }
        if (sel) {
            int slot = atomicAdd(&s_slot, 1);
            g_Mtop[bh * UU + slot] = j;
            g_rank[bh * LL + j] = slot;
        }
    }
}

// ---------------- launch 5: scores (512 blocks) ∥ csum_scan (256 blocks) ----------------
#define KT 64
#define NSCBLK (BH * (LL / KT))     // 512
__global__ void k_scores_scan(float* __restrict__ ctx) {
    __shared__ float shp[CH * 64];          // 32768 bytes, dual-purpose
    int blk = blockIdx.x, t = threadIdx.x;
    if (blk < NSCBLK) {
        float* qtop = shp;                  // UU*DK = 2560 floats
        float* kt   = shp + UU * DK;        // KT*65 = 4160 floats
        int bh = blk >> 5, l0 = (blk & 31) * KT;
        for (int j = t; j < UU * DK; j += 256) {
            int u = j >> 6, d = j & 63;
            int rl = g_Mtop[bh * UU + u];
            qtop[j] = g_q[((((size_t)bh << 11) + rl) << 6) + d];
        }
        for (int j = t; j < KT * DK; j += 256) {
            int li = j >> 6, d = j & 63;
            kt[li * 65 + d] = g_k[((((size_t)bh << 11) + l0 + li) << 6) + d];
        }
        __syncthreads();
        int lsub = t & 63, ug = t >> 6;
        float accv[10];
        #pragma unroll
        for (int g = 0; g < 10; g++) accv[g] = 0.f;
        for (int d = 0; d < 64; d++) {
            float kv = kt[lsub * 65 + d];
            #pragma unroll
            for (int g = 0; g < 10; g++)
                accv[g] += qtop[(ug + 4 * g) * 64 + d] * kv;
        }
        #pragma unroll
        for (int g = 0; g < 10; g++) {
            int u = ug + 4 * g;
            g_scores[((size_t)(bh * UU + u) << 11) + l0 + lsub] = accv[g] * 0.125f;
        }
    } else {
        float* vsh = shp;                   // CH*64 = 8192 floats
        int b2 = blk - NSCBLK;              // 0..255
        int bh = b2 >> 4, c = b2 & 15;
        const float4* vb = (const float4*)(g_v + ((((size_t)bh << 11) + c * CH) << 6));
        float4* vs4 = (float4*)vsh;
        for (int j = t; j < CH * 16; j += 256) vs4[j] = vb[j];
        __syncthreads();
        if (t < 64) {
            float run = g_offs[(bh * NCH + c) * 64 + t];
            for (int i = 0; i < CH; i++) { run += vsh[i * 64 + t]; vsh[i * 64 + t] = run; }
        }
        __syncthreads();
        float4* ob = (float4*)(ctx + ((((size_t)bh << 11) + c * CH) << 6));
        for (int j = t; j < CH * 16; j += 256) ob[j] = vs4[j];
    }
}

// ---------------- launch 6: softmax stats; overwrites scores with exp(s-mx) ----------------
__global__ void k_stats() {
    __shared__ float red[256];
    int r = blockIdx.x, t = threadIdx.x;
    float* s = g_scores + ((size_t)r << 11);
    float mx = -INFINITY;
    for (int j = t; j < LL; j += 256) mx = fmaxf(mx, s[j]);
    red[t] = mx; __syncthreads();
    for (int o = 128; o; o >>= 1) { if (t < o) red[t] = fmaxf(red[t], red[t + o]); __syncthreads(); }
    mx = red[0]; __syncthreads();
    float sm = 0.f;
    for (int j = t; j < LL; j += 256) {
        float e = expf(s[j] - mx);
        s[j] = e;
        sm += e;
    }
    red[t] = sm; __syncthreads();
    for (int o = 128; o; o >>= 1) { if (t < o) red[t] += red[t + o]; __syncthreads(); }
    if (t == 0) { g_mx[r] = mx; g_inv[r] = 1.0f / red[0]; }
}

// ---------------- launch 7: upd partials = attn @ V ----------------
__global__ void k_upd() {
    __shared__ float vsh[64 * 64];
    __shared__ float ash[UU * 64];
    __shared__ float sinv[UU];
    int bh = blockIdx.y, ls = blockIdx.x;
    int t = threadIdx.x;
    if (t < UU) sinv[t] = g_inv[bh * UU + t];

    int lane2 = (t & 31) * 2, ug = t >> 5;
    float acc[5][2];
    #pragma unroll
    for (int uu = 0; uu < 5; uu++) { acc[uu][0] = 0.f; acc[uu][1] = 0.f; }

    for (int tile = 0; tile < 4; tile++) {
        int l0 = ls * 256 + tile * 64;
        __syncthreads();
        const float4* vb = (const float4*)(g_v + ((((size_t)bh << 11) + l0) << 6));
        float4* vs4 = (float4*)vsh;
        for (int j = t; j < 64 * 16; j += 256) vs4[j] = vb[j];
        for (int j = t; j < UU * 64; j += 256) {
            int u = j >> 6, li = j & 63;
            ash[j] = g_scores[((size_t)(bh * UU + u) << 11) + l0 + li] * sinv[u];
        }
        __syncthreads();
        for (int li = 0; li < 64; li++) {
            float v0 = vsh[li * 64 + lane2], v1 = vsh[li * 64 + lane2 + 1];
            #pragma unroll
            for (int uu = 0; uu < 5; uu++) {
                float a = ash[(ug * 5 + uu) * 64 + li];
                acc[uu][0] += a * v0;
                acc[uu][1] += a * v1;
            }
        }
    }
    #pragma unroll
    for (int uu = 0; uu < 5; uu++) {
        int r = bh * UU + ug * 5 + uu;
        g_updp[((size_t)ls * BH * UU + r) * 64 + lane2]     = acc[uu][0];
        g_updp[((size_t)ls * BH * UU + r) * 64 + lane2 + 1] = acc[uu][1];
    }
}

// ---------------- launch 8: attns output (32768 blocks) ∥ scatter (640 blocks) ----------------
__global__ void k_attns_scatter(float* __restrict__ ctx, float* __restrict__ attns) {
    int blk = blockIdx.x, t = threadIdx.x;
    if (blk >= NROWS) {
        int r = blk - NROWS;                // bh*UU + u
        if (t < 64) {
            int bh = r / UU;
            int l = g_Mtop[r];
            float s = 0.f;
            #pragma unroll
            for (int p = 0; p < 8; p++) s += g_updp[((size_t)p * BH * UU + r) * 64 + t];
            ctx[((((size_t)bh << 11) + l) << 6) + t] = s;
        }
        return;
    }
    int row = blk;
    int bh = row >> 11;
    int r = g_rank[row];
    float* out = attns + ((size_t)row << 11);
    if (r < 0) {
        float4 c = make_float4(1.0f / LL, 1.0f / LL, 1.0f / LL, 1.0f / LL);
        float4* o4 = (float4*)out;
        o4[t] = c;
        o4[t + 256] = c;
    } else {
        float inv = g_inv[bh * UU + r];
        const float* s = g_scores + ((size_t)(bh * UU + r) << 11);
        #pragma unroll
        for (int j = 0; j < 2; j++) {
            int base = (t + j * 256) * 4;
            float4 sv = *(const float4*)(s + base);
            float4 ov;
            ov.x = sv.x * inv;
            ov.y = sv.y * inv;
            ov.z = sv.z * inv;
            ov.w = sv.w * inv;
            *(float4*)(out + base) = ov;
        }
    }
}

// ---------------- launch ----------------
extern "C" void kernel_launch(void* const* d_in, const int* in_sizes, int n_in,
                              void* d_out, int out_size) {
    const float* x  = (const float*)d_in[0];
    const float* Wq = (const float*)d_in[1];
    const float* bq = (const float*)d_in[2];
    const float* Wk = (const float*)d_in[3];
    const float* bk = (const float*)d_in[4];
    const float* Wv = (const float*)d_in[5];
    const float* bv = (const float*)d_in[6];
    const unsigned int* idxraw = (const unsigned int*)d_in[7];

    float* ctx   = (float*)d_out;
    float* attns = ctx + (size_t)BB * LL * DD;

    static int smem_set = 0;
    if (!smem_set) {
        cudaFuncSetAttribute(gemm_mma, cudaFuncAttributeMaxDynamicSharedMemorySize, GEMM_SMEM);
        smem_set = 1;
    }

    k_pre<<<16 + NCVX + NCVW, 256>>>(idxraw, x, Wq, Wk, Wv);
    gemm_mma<<<dim3(12, 32), 256, GEMM_SMEM>>>(bq, bk, bv);
    k_samp_part<<<NROWS / 8 + BH * NCH, 256>>>();
    k_topk_off<<<BH * 2, 256>>>();
    k_scores_scan<<<NSCBLK + BH * NCH, 256>>>(ctx);
    k_stats<<<BH * UU, 256>>>();
    k_upd<<<dim3(8, BH), 256>>>();
    k_attns_scatter<<<NROWS + BH * UU, 256>>>(ctx, attns);
}

// round 17
// speedup vs baseline: 1.1827x; 1.0479x over previous
#include <cuda_runtime.h>
#include <cuda_fp16.h>
#include <math.h>

#define BB 2
#define LL 2048
#define DD 512
#define HH 8
#define DK 64
#define SK 40
#define UU 40
#define BH 16            // BB*HH
#define NROWS 32768      // BH*LL
#define NCH 16           // cumsum chunks per (b,h)
#define CH 128           // L per chunk

// ---------------- scratch (device globals; no allocation) ----------------
__device__ float g_q[BB*HH*LL*DK];
__device__ float g_k[BB*HH*LL*DK];
__device__ float g_v[BB*HH*LL*DK];
__device__ float g_scores[BH*UU*LL];
__device__ float g_M[NROWS];
__device__ int   g_Mtop[BH*UU];
__device__ int   g_rank[NROWS];
__device__ float g_mx[BH*UU];
__device__ float g_inv[BH*UU];
__device__ float g_part[BH*NCH*DK];
__device__ float g_offs[BH*NCH*DK];
__device__ float g_updp[8*BH*UU*DK];
__device__ int   g_idx[LL*SK];
// fp16x3 split operands (16B-aligned for float4 access)
__device__ __align__(16) __half g_xh[BB*LL*DD];
__device__ __align__(16) __half g_xl[BB*LL*DD];
__device__ __align__(16) __half g_wh[3*DD*DD];
__device__ __align__(16) __half g_wl[3*DD*DD];

// ---------------- helpers ----------------
__device__ __forceinline__ void cvt_store(float4 v, __half2* dh, __half2* dl) {
    __half h0 = __float2half(v.x), h1 = __float2half(v.y);
    __half h2 = __float2half(v.z), h3 = __float2half(v.w);
    __half l0 = __float2half(v.x - __half2float(h0));
    __half l1 = __float2half(v.y - __half2float(h1));
    __half l2 = __float2half(v.z - __half2float(h2));
    __half l3 = __float2half(v.w - __half2float(h3));
    dh[0] = __halves2half2(h0, h1); dh[1] = __halves2half2(h2, h3);
    dl[0] = __halves2half2(l0, l1); dl[1] = __halves2half2(l2, l3);
}

// ---------------- launch 1: idx normalize + hi/lo split converters (union) ----------------
#define NCVX (BB*LL*DD/4/256)   // 2048 blocks for x
#define NCVW (3*DD*DD/4/256)    // 768 blocks for W
__global__ void k_pre(const unsigned int* __restrict__ raw,
                      const float* __restrict__ x, const float* __restrict__ Wq,
                      const float* __restrict__ Wk, const float* __restrict__ Wv) {
    int blk = blockIdx.x, t = threadIdx.x;
    if (blk < 16) {
        __shared__ int s_flag;
        const int nelem = LL * SK;
        int per = nelem / 16;
        int wbase = blk * per;
        if (t == 0) s_flag = 0;
        __syncthreads();
        int local = 0;
        for (int j = t * 2 + 1; j < per; j += 512)
            if (raw[wbase + j] != 0u) local = 1;
        if (local) atomicOr(&s_flag, 1);
        __syncthreads();
        int is32 = s_flag;
        for (int e = wbase + t; e < wbase + per; e += 256)
            g_idx[e] = is32 ? (int)raw[e] : (int)raw[2 * e];
    } else if (blk < 16 + NCVX) {
        int i4 = (blk - 16) * 256 + t;
        float4 v = ((const float4*)x)[i4];
        cvt_store(v, (__half2*)g_xh + i4*2, (__half2*)g_xl + i4*2);
    } else {
        int k = (blk - 16 - NCVX) * 256 + t;
        const int per = DD*DD/4;
        const float* src = (k < per) ? Wq : (k < 2*per) ? Wk : Wv;
        int j4 = (k < per) ? k : (k < 2*per) ? k - per : k - 2*per;
        float4 v = ((const float4*)src)[j4];
        cvt_store(v, (__half2*)g_wh + k*2, (__half2*)g_wl + k*2);
    }
}

// ---------------- launch 2: QKV projection via fp16x3 tensor-core mma ----------------
#define SROW 24            // halves per smem row (16 data + 8 pad) = 48B
#define PLANE (128*SROW)
#define NSTAGE 3
#define GEMM_SMEM (NSTAGE * 2 * 2 * PLANE * 2)   // 73728 bytes

#define CP_ASYNC16(dst, src) \
    asm volatile("cp.async.ca.shared.global [%0], [%1], 16;" :: "r"(dst), "l"(src))
#define CP_COMMIT() asm volatile("cp.async.commit_group;")
#define CP_WAIT1()  asm volatile("cp.async.wait_group 1;")
#define CP_WAIT0()  asm volatile("cp.async.wait_group 0;")

__device__ __forceinline__ void ldm4(unsigned int addr, unsigned int* r) {
    asm volatile("ldmatrix.sync.aligned.m8n8.x4.shared.b16 {%0,%1,%2,%3}, [%4];"
                 : "=r"(r[0]), "=r"(r[1]), "=r"(r[2]), "=r"(r[3]) : "r"(addr));
}
__device__ __forceinline__ void mma16816(float* c, const unsigned int* a, const unsigned int* b) {
    asm volatile("mma.sync.aligned.m16n8k16.row.col.f32.f16.f16.f32 "
                 "{%0,%1,%2,%3}, {%4,%5,%6,%7}, {%8,%9}, {%0,%1,%2,%3};"
                 : "+f"(c[0]), "+f"(c[1]), "+f"(c[2]), "+f"(c[3])
                 : "r"(a[0]), "r"(a[1]), "r"(a[2]), "r"(a[3]), "r"(b[0]), "r"(b[1]));
}

__global__ __launch_bounds__(256, 2) void gemm_mma(
    const float* __restrict__ bq, const float* __restrict__ bk, const float* __restrict__ bv) {
    extern __shared__ __align__(16) __half dsm[];
    int tid = threadIdx.x, lane = tid & 31, wid = tid >> 5;
    int warpM = wid >> 1, warpN = wid & 1;
    int m0 = blockIdx.y * 128, n0 = blockIdx.x * 128;
    int w = n0 >> 9;
    const float* bias = (w == 0) ? bq : (w == 1) ? bk : bv;
    float* outp       = (w == 0) ? g_q : (w == 1) ? g_k : g_v;
    int i0 = n0 & 511;

    int grow = tid >> 1, gkh = tid & 1;
    const __half* pxh = &g_xh[(size_t)(m0 + grow) * 512 + gkh * 8];
    const __half* pxl = &g_xl[(size_t)(m0 + grow) * 512 + gkh * 8];
    const __half* pwh = &g_wh[(size_t)(w * 512 + i0 + grow) * 512 + gkh * 8];
    const __half* pwl = &g_wl[(size_t)(w * 512 + i0 + grow) * 512 + gkh * 8];
    unsigned int dst_off = (unsigned int)((grow * SROW + gkh * 8) * 2);
    unsigned int base = (unsigned int)__cvta_generic_to_shared(dsm);
    const unsigned int PB = PLANE * 2;
    const unsigned int BOFF = 6 * PB;

    float acc[2][8][4];
    #pragma unroll
    for (int i = 0; i < 2; i++)
        #pragma unroll
        for (int j = 0; j < 8; j++)
            #pragma unroll
            for (int c = 0; c < 4; c++) acc[i][j][c] = 0.f;

    #pragma unroll
    for (int s = 0; s < 2; s++) {
        unsigned int sa = base + (s*2)*PB + dst_off;
        unsigned int sb = base + BOFF + (s*2)*PB + dst_off;
        CP_ASYNC16(sa,      pxh + s * 16);
        CP_ASYNC16(sa + PB, pxl + s * 16);
        CP_ASYNC16(sb,      pwh + s * 16);
        CP_ASYNC16(sb + PB, pwl + s * 16);
        CP_COMMIT();
    }

    int aRow = warpM * 32 + (lane & 15), aK = (lane >> 4) * 8;
    int bRow = warpN * 64 + 8 * (lane >> 4) + (lane & 7), bK = ((lane >> 3) & 1) * 8;

    #pragma unroll 1
    for (int ks = 0; ks < 32; ks++) {
        int cur = ks % NSTAGE;
        if (ks < 31) { CP_WAIT1(); } else { CP_WAIT0(); }
        __syncthreads();

        if (ks + 2 < 32) {
            int st = (ks + 2) % NSTAGE;
            unsigned int sa = base + (st*2)*PB + dst_off;
            unsigned int sb = base + BOFF + (st*2)*PB + dst_off;
            CP_ASYNC16(sa,      pxh + (ks + 2) * 16);
            CP_ASYNC16(sa + PB, pxl + (ks + 2) * 16);
            CP_ASYNC16(sb,      pwh + (ks + 2) * 16);
            CP_ASYNC16(sb + PB, pwl + (ks + 2) * 16);
            CP_COMMIT();
        }

        unsigned int afr[2][2][4];
        #pragma unroll
        for (int comp = 0; comp < 2; comp++)
            #pragma unroll
            for (int mt = 0; mt < 2; mt++) {
                unsigned int ad = base + (cur*2 + comp)*PB +
                    (unsigned int)(((aRow + mt * 16) * SROW + aK) * 2);
                ldm4(ad, afr[comp][mt]);
            }
        #pragma unroll
        for (int np = 0; np < 4; np++) {
            unsigned int bfr[2][4];
            #pragma unroll
            for (int comp = 0; comp < 2; comp++) {
                unsigned int bd = base + BOFF + (cur*2 + comp)*PB +
                    (unsigned int)(((bRow + np * 16) * SROW + bK) * 2);
                ldm4(bd, bfr[comp]);
            }
            #pragma unroll
            for (int mt = 0; mt < 2; mt++) {
                #pragma unroll
                for (int half = 0; half < 2; half++) {
                    int nt = np * 2 + half;
                    unsigned int bh_[2] = {bfr[0][half*2], bfr[0][half*2+1]};
                    unsigned int bl_[2] = {bfr[1][half*2], bfr[1][half*2+1]};
                    mma16816(acc[mt][nt], afr[0][mt], bh_);
                    mma16816(acc[mt][nt], afr[0][mt], bl_);
                    mma16816(acc[mt][nt], afr[1][mt], bh_);
                }
            }
        }
    }

    #pragma unroll
    for (int mt = 0; mt < 2; mt++) {
        int mr = m0 + warpM * 32 + mt * 16 + (lane >> 2);
        #pragma unroll
        for (int nt = 0; nt < 8; nt++) {
            int col = warpN * 64 + nt * 8 + 2 * (lane & 3);
            int i1 = i0 + col, i2 = i1 + 1;
            #pragma unroll
            for (int rh = 0; rh < 2; rh++) {
                int m = mr + rh * 8;
                int bh_ = (m >> 11) * HH;
                int l = m & 2047;
                float c0 = acc[mt][nt][rh*2], c1 = acc[mt][nt][rh*2+1];
                outp[((((size_t)(bh_ + (i1 >> 6))) << 11) + l) * 64 + (i1 & 63)] = c0 + bias[i1];
                outp[((((size_t)(bh_ + (i2 >> 6))) << 11) + l) * 64 + (i2 & 63)] = c1 + bias[i2];
            }
        }
    }
}

// ---------------- launch 3: sampled scores -> M (4096 blocks) ∥ csum_part (256 blocks) ----------------
__global__ __launch_bounds__(256) void k_samp_part() {
    int blk = blockIdx.x, t = threadIdx.x;
    if (blk < NROWS / 8) {
        __shared__ int sidx[8][SK];
        int wid = t >> 5, lane = t & 31;
        int row = blk * 8 + wid;
        int bh = row >> 11, l = row & 2047;
        float4 qf = ((const float4*)(g_q + ((size_t)row << 6)))[lane & 15];
        sidx[wid][lane] = g_idx[l * SK + lane];
        if (lane < SK - 32) sidx[wid][lane + 32] = g_idx[l * SK + lane + 32];
        __syncwarp();
        int half = lane >> 4;
        float mx = -INFINITY, sm = 0.f;
        const float* kb = g_k + ((size_t)bh << 17);
        #pragma unroll
        for (int it = 0; it < SK / 2; it++) {
            int idx = sidx[wid][2 * it + half];
            float4 kf = ((const float4*)(kb + ((size_t)idx << 6)))[lane & 15];
            float p = qf.x*kf.x + qf.y*kf.y + qf.z*kf.z + qf.w*kf.w;
            p += __shfl_xor_sync(0xffffffffu, p, 1);
            p += __shfl_xor_sync(0xffffffffu, p, 2);
            p += __shfl_xor_sync(0xffffffffu, p, 4);
            p += __shfl_xor_sync(0xffffffffu, p, 8);
            mx = fmaxf(mx, p);
            sm += p;
        }
        mx = fmaxf(mx, __shfl_xor_sync(0xffffffffu, mx, 16));
        sm += __shfl_xor_sync(0xffffffffu, sm, 16);
        if (lane == 0) g_M[row] = mx - sm * (1.0f / LL);
    } else {
        __shared__ float red[256];
        int b2 = blk - NROWS / 8;           // 0..255
        int bh = b2 >> 4, c = b2 & 15;
        int d = t & 63, p = t >> 6;
        const float* vb = g_v + ((((size_t)bh << 11) + c * CH) << 6);
        float s = 0.f;
        for (int i = 0; i < 32; i++) s += vb[(p * 32 + i) * 64 + d];
        red[t] = s; __syncthreads();
        if (t < 64)
            g_part[b2 * 64 + t] = red[t] + red[t + 64] + red[t + 128] + red[t + 192];
    }
}

// ---------------- launch 4: top-40 radix select (ballot tie-rank) ∥ csum_off ----------------
__global__ void k_topk_off() {
    int blk = blockIdx.x, t = threadIdx.x;
    if (blk >= BH) {
        int bh = blk - BH;
        if (t < 64) {
            float run = 0.f;
            for (int c = 0; c < NCH; c++) {
                g_offs[(bh * NCH + c) * 64 + t] = run;
                run += g_part[(bh * NCH + c) * 64 + t];
            }
        }
        return;
    }
    __shared__ unsigned int uvals[LL];
    __shared__ int hist[256];
    __shared__ unsigned int eqmask[8][8];   // [stride][warp]
    __shared__ unsigned int s_prefix;
    __shared__ int s_want, s_slot;
    int bh = blk;
    int wid = t >> 5, lane = t & 31;
    for (int j = t; j < LL; j += 256) {
        unsigned int b = __float_as_uint(g_M[bh * LL + j]);
        uvals[j] = (b & 0x80000000u) ? ~b : (b | 0x80000000u);
        g_rank[bh * LL + j] = -1;
    }
    if (t == 0) { s_want = UU; s_prefix = 0u; s_slot = 0; }
    __syncthreads();

    #pragma unroll
    for (int level = 0; level < 4; level++) {
        int shift = 24 - level * 8;
        unsigned int mask = (level == 0) ? 0u : (0xFFFFFFFFu << (32 - 8 * level));
        hist[t] = 0;
        __syncthreads();
        unsigned int pref = s_prefix;
        for (int j = t; j < LL; j += 256) {
            unsigned int u = uvals[j];
            if ((u & mask) == pref)
                atomicAdd(&hist[(u >> shift) & 0xFF], 1);
        }
        __syncthreads();
        // warp 0: suffix-scan 256 bins (8 per lane) via shfl; pick crossing bin
        if (t < 32) {
            int base_ = t * 8;
            int loc[8];
            int s = 0;
            #pragma unroll
            for (int i = 7; i >= 0; i--) { s += hist[base_ + i]; loc[i] = s; }
            int hi = s;
            #pragma unroll
            for (int o = 1; o < 32; o <<= 1) {
                int v = __shfl_down_sync(0xffffffffu, hi, o);
                if (t + o < 32) hi += v;
            }
            int above_lanes = hi - s;
            int want = s_want;
            #pragma unroll
            for (int i = 0; i < 8; i++) {
                int sfx = loc[i] + above_lanes;
                int abv = ((i < 7) ? loc[i + 1] : 0) + above_lanes;
                if (sfx >= want && abv < want) {
                    s_prefix = pref | ((unsigned int)(base_ + i) << shift);
                    s_want = want - abv;
                }
            }
        }
        __syncthreads();
    }

    unsigned int T = s_prefix;
    int r = s_want;
    // ballot pass: per-stride, per-warp equality masks (global index j = s*256 + wid*32 + lane)
    #pragma unroll
    for (int s = 0; s < 8; s++) {
        unsigned int m = __ballot_sync(0xffffffffu, uvals[s * 256 + t] == T);
        if (lane == 0) eqmask[s][wid] = m;
    }
    __syncthreads();
    #pragma unroll
    for (int s = 0; s < 8; s++) {
        int j = s * 256 + t;
        unsigned int u = uvals[j];
        bool sel = false;
        if (u > T) sel = true;
        else if (u == T) {
            int rank_eq = 0;
            for (int s2 = 0; s2 < s; s2++)
                #pragma unroll
                for (int w2 = 0; w2 < 8; w2++) rank_eq += __popc(eqmask[s2][w2]);
            for (int w2 = 0; w2 < wid; w2++) rank_eq += __popc(eqmask[s][w2]);
            rank_eq += __popc(eqmask[s][wid] & ((1u << lane) - 1u));
            sel = (rank_eq < r);
        }
        if (sel) {
            int slot = atomicAdd(&s_slot, 1);
            g_Mtop[bh * UU + slot] = j;
            g_rank[bh * LL + j] = slot;
        }
    }
}

// ---------------- launch 5: scores (512 blocks) ∥ csum_scan (256 blocks) ----------------
#define KT 64
#define NSCBLK (BH * (LL / KT))     // 512
__global__ void k_scores_scan(float* __restrict__ ctx) {
    __shared__ float shp[CH * 64];          // 32768 bytes, dual-purpose
    int blk = blockIdx.x, t = threadIdx.x;
    if (blk < NSCBLK) {
        float* qtop = shp;                  // UU*DK = 2560 floats
        float* kt   = shp + UU * DK;        // KT*65 = 4160 floats
        int bh = blk >> 5, l0 = (blk & 31) * KT;
        for (int j = t; j < UU * DK; j += 256) {
            int u = j >> 6, d = j & 63;
            int rl = g_Mtop[bh * UU + u];
            qtop[j] = g_q[((((size_t)bh << 11) + rl) << 6) + d];
        }
        for (int j = t; j < KT * DK; j += 256) {
            int li = j >> 6, d = j & 63;
            kt[li * 65 + d] = g_k[((((size_t)bh << 11) + l0 + li) << 6) + d];
        }
        __syncthreads();
        int lsub = t & 63, ug = t >> 6;
        float accv[10];
        #pragma unroll
        for (int g = 0; g < 10; g++) accv[g] = 0.f;
        for (int d = 0; d < 64; d++) {
            float kv = kt[lsub * 65 + d];
            #pragma unroll
            for (int g = 0; g < 10; g++)
                accv[g] += qtop[(ug + 4 * g) * 64 + d] * kv;
        }
        #pragma unroll
        for (int g = 0; g < 10; g++) {
            int u = ug + 4 * g;
            g_scores[((size_t)(bh * UU + u) << 11) + l0 + lsub] = accv[g] * 0.125f;
        }
    } else {
        float* vsh = shp;                   // CH*64 = 8192 floats
        int b2 = blk - NSCBLK;              // 0..255
        int bh = b2 >> 4, c = b2 & 15;
        const float4* vb = (const float4*)(g_v + ((((size_t)bh << 11) + c * CH) << 6));
        float4* vs4 = (float4*)vsh;
        for (int j = t; j < CH * 16; j += 256) vs4[j] = vb[j];
        __syncthreads();
        if (t < 64) {
            float run = g_offs[(bh * NCH + c) * 64 + t];
            for (int i = 0; i < CH; i++) { run += vsh[i * 64 + t]; vsh[i * 64 + t] = run; }
        }
        __syncthreads();
        float4* ob = (float4*)(ctx + ((((size_t)bh << 11) + c * CH) << 6));
        for (int j = t; j < CH * 16; j += 256) ob[j] = vs4[j];
    }
}

// ---------------- launch 6: softmax stats; overwrites scores with exp(s-mx) ----------------
__global__ void k_stats() {
    __shared__ float red[256];
    int r = blockIdx.x, t = threadIdx.x;
    float* s = g_scores + ((size_t)r << 11);
    float mx = -INFINITY;
    for (int j = t; j < LL; j += 256) mx = fmaxf(mx, s[j]);
    red[t] = mx; __syncthreads();
    for (int o = 128; o; o >>= 1) { if (t < o) red[t] = fmaxf(red[t], red[t + o]); __syncthreads(); }
    mx = red[0]; __syncthreads();
    float sm = 0.f;
    for (int j = t; j < LL; j += 256) {
        float e = expf(s[j] - mx);
        s[j] = e;
        sm += e;
    }
    red[t] = sm; __syncthreads();
    for (int o = 128; o; o >>= 1) { if (t < o) red[t] += red[t + o]; __syncthreads(); }
    if (t == 0) { g_mx[r] = mx; g_inv[r] = 1.0f / red[0]; }
}

// ---------------- launch 7: upd partials = attn @ V ----------------
__global__ void k_upd() {
    __shared__ float vsh[64 * 64];
    __shared__ float ash[UU * 64];
    __shared__ float sinv[UU];
    int bh = blockIdx.y, ls = blockIdx.x;
    int t = threadIdx.x;
    if (t < UU) sinv[t] = g_inv[bh * UU + t];

    int lane2 = (t & 31) * 2, ug = t >> 5;
    float acc[5][2];
    #pragma unroll
    for (int uu = 0; uu < 5; uu++) { acc[uu][0] = 0.f; acc[uu][1] = 0.f; }

    for (int tile = 0; tile < 4; tile++) {
        int l0 = ls * 256 + tile * 64;
        __syncthreads();
        const float4* vb = (const float4*)(g_v + ((((size_t)bh << 11) + l0) << 6));
        float4* vs4 = (float4*)vsh;
        for (int j = t; j < 64 * 16; j += 256) vs4[j] = vb[j];
        for (int j = t; j < UU * 64; j += 256) {
            int u = j >> 6, li = j & 63;
            ash[j] = g_scores[((size_t)(bh * UU + u) << 11) + l0 + li] * sinv[u];
        }
        __syncthreads();
        for (int li = 0; li < 64; li++) {
            float v0 = vsh[li * 64 + lane2], v1 = vsh[li * 64 + lane2 + 1];
            #pragma unroll
            for (int uu = 0; uu < 5; uu++) {
                float a = ash[(ug * 5 + uu) * 64 + li];
                acc[uu][0] += a * v0;
                acc[uu][1] += a * v1;
            }
        }
    }
    #pragma unroll
    for (int uu = 0; uu < 5; uu++) {
        int r = bh * UU + ug * 5 + uu;
        g_updp[((size_t)ls * BH * UU + r) * 64 + lane2]     = acc[uu][0];
        g_updp[((size_t)ls * BH * UU + r) * 64 + lane2 + 1] = acc[uu][1];
    }
}

// ---------------- launch 8: attns output (32768 blocks) ∥ scatter (640 blocks) ----------------
__global__ void k_attns_scatter(float* __restrict__ ctx, float* __restrict__ attns) {
    int blk = blockIdx.x, t = threadIdx.x;
    if (blk >= NROWS) {
        int r = blk - NROWS;                // bh*UU + u
        if (t < 64) {
            int bh = r / UU;
            int l = g_Mtop[r];
            float s = 0.f;
            #pragma unroll
            for (int p = 0; p < 8; p++) s += g_updp[((size_t)p * BH * UU + r) * 64 + t];
            ctx[((((size_t)bh << 11) + l) << 6) + t] = s;
        }
        return;
    }
    int row = blk;
    int bh = row >> 11;
    int r = g_rank[row];
    float* out = attns + ((size_t)row << 11);
    if (r < 0) {
        float4 c = make_float4(1.0f / LL, 1.0f / LL, 1.0f / LL, 1.0f / LL);
        float4* o4 = (float4*)out;
        o4[t] = c;
        o4[t + 256] = c;
    } else {
        float inv = g_inv[bh * UU + r];
        const float* s = g_scores + ((size_t)(bh * UU + r) << 11);
        #pragma unroll
        for (int j = 0; j < 2; j++) {
            int base = (t + j * 256) * 4;
            float4 sv = *(const float4*)(s + base);
            float4 ov;
            ov.x = sv.x * inv;
            ov.y = sv.y * inv;
            ov.z = sv.z * inv;
            ov.w = sv.w * inv;
            *(float4*)(out + base) = ov;
        }
    }
}

// ---------------- launch ----------------
extern "C" void kernel_launch(void* const* d_in, const int* in_sizes, int n_in,
                              void* d_out, int out_size) {
    const float* x  = (const float*)d_in[0];
    const float* Wq = (const float*)d_in[1];
    const float* bq = (const float*)d_in[2];
    const float* Wk = (const float*)d_in[3];
    const float* bk = (const float*)d_in[4];
    const float* Wv = (const float*)d_in[5];
    const float* bv = (const float*)d_in[6];
    const unsigned int* idxraw = (const unsigned int*)d_in[7];

    float* ctx   = (float*)d_out;
    float* attns = ctx + (size_t)BB * LL * DD;

    static int smem_set = 0;
    if (!smem_set) {
        cudaFuncSetAttribute(gemm_mma, cudaFuncAttributeMaxDynamicSharedMemorySize, GEMM_SMEM);
        smem_set = 1;
    }

    k_pre<<<16 + NCVX + NCVW, 256>>>(idxraw, x, Wq, Wk, Wv);
    gemm_mma<<<dim3(12, 32), 256, GEMM_SMEM>>>(bq, bk, bv);
    k_samp_part<<<NROWS / 8 + BH * NCH, 256>>>();
    k_topk_off<<<BH * 2, 256>>>();
    k_scores_scan<<<NSCBLK + BH * NCH, 256>>>(ctx);
    k_stats<<<BH * UU, 256>>>();
    k_upd<<<dim3(8, BH), 256>>>();
    k_attns_scatter<<<NROWS + BH * UU, 256>>>(ctx, attns);
}